// round 14
// baseline (speedup 1.0000x reference)
#include <cuda_runtime.h>
#include <cuda_fp16.h>
#include <cstdint>

#define NN 8192
#define DD 256

// ---------------- scratch (device globals; no allocation allowed) ----------
__device__ float  g_q[NN * DD];
__device__ float  g_v[NN * DD];
__device__ __half g_xh[NN * DD];              // x hi split
__device__ __half g_xl[NN * DD];              // x lo split
__device__ __half g_wh[3 * DD * DD];          // Wq|Wk|Wv hi split
__device__ __half g_wl[3 * DD * DD];          // Wq|Wk|Wv lo split
__device__ __half g_kh[NN * DD];              // k hi split [j][d]
__device__ __half g_kl[NN * DD];              // k lo split
__device__ float  g_spart[4 * NN];            // deterministic partials
__device__ float  g_alpha[NN];                // exp(s - max) (unnormalized)
__device__ float  g_inv;                      // 1 / sum(exp)

// ---------------- PTX helpers (base sm_80+ ISA only) ------------------------
__device__ __forceinline__ uint32_t cvta_smem(const void* p) {
    uint32_t a;
    asm("{ .reg .u64 t; cvta.to.shared.u64 t, %1; cvt.u32.u64 %0, t; }"
        : "=r"(a) : "l"(p));
    return a;
}
__device__ __forceinline__ void cp16(uint32_t dst, const void* src) {
    asm volatile("cp.async.cg.shared.global [%0], [%1], 16;" :: "r"(dst), "l"(src));
}
__device__ __forceinline__ void cp_commit() {
    asm volatile("cp.async.commit_group;" ::: "memory");
}
template <int N>
__device__ __forceinline__ void cp_wait() {
    asm volatile("cp.async.wait_group %0;" :: "n"(N) : "memory");
}
__device__ __forceinline__ void ldm_x4(uint32_t addr, uint32_t& r0, uint32_t& r1,
                                       uint32_t& r2, uint32_t& r3) {
    asm volatile("ldmatrix.sync.aligned.m8n8.x4.shared.b16 {%0,%1,%2,%3}, [%4];"
                 : "=r"(r0), "=r"(r1), "=r"(r2), "=r"(r3) : "r"(addr));
}
__device__ __forceinline__ void ldm_x4_t(uint32_t addr, uint32_t& r0, uint32_t& r1,
                                         uint32_t& r2, uint32_t& r3) {
    asm volatile("ldmatrix.sync.aligned.m8n8.x4.trans.shared.b16 {%0,%1,%2,%3}, [%4];"
                 : "=r"(r0), "=r"(r1), "=r"(r2), "=r"(r3) : "r"(addr));
}
__device__ __forceinline__ void mma16816(float* c, const uint32_t* a,
                                         uint32_t b0, uint32_t b1) {
    asm volatile(
        "mma.sync.aligned.m16n8k16.row.col.f32.f16.f16.f32 "
        "{%0,%1,%2,%3}, {%4,%5,%6,%7}, {%8,%9}, {%0,%1,%2,%3};"
        : "+f"(c[0]), "+f"(c[1]), "+f"(c[2]), "+f"(c[3])
        : "r"(a[0]), "r"(a[1]), "r"(a[2]), "r"(a[3]), "r"(b0), "r"(b1));
}

// ---------------------------------------------------------------------------
// fused x-split + W-split
// ---------------------------------------------------------------------------
__global__ __launch_bounds__(256) void split_kernel(const float* __restrict__ x,
                                                    const float* __restrict__ Wq,
                                                    const float* __restrict__ Wk,
                                                    const float* __restrict__ Wv)
{
    const int X4 = NN * DD / 4;
    const int W4 = DD * DD / 4;
    int i4 = blockIdx.x * blockDim.x + threadIdx.x;
    const float* src;
    __half *dh, *dl;
    size_t off;
    if (i4 < X4) {
        src = x; dh = g_xh; dl = g_xl; off = (size_t)i4 * 4;
    } else if (i4 < X4 + 3 * W4) {
        int r = i4 - X4;
        int z = r / W4;
        int w = r - z * W4;
        src = (z == 0) ? Wq : (z == 1) ? Wk : Wv;
        dh = g_wh + (size_t)z * DD * DD;
        dl = g_wl + (size_t)z * DD * DD;
        off = (size_t)w * 4;
    } else {
        return;
    }
    float4 v4 = *(const float4*)(src + off);
    float vs[4] = {v4.x, v4.y, v4.z, v4.w};
    __half hi[4], lo[4];
    #pragma unroll
    for (int i = 0; i < 4; i++) {
        hi[i] = __float2half_rn(vs[i]);
        lo[i] = __float2half_rn(vs[i] - __half2float(hi[i]));
    }
    *(__half2*)(dh + off)     = __halves2half2(hi[0], hi[1]);
    *(__half2*)(dh + off + 2) = __halves2half2(hi[2], hi[3]);
    *(__half2*)(dl + off)     = __halves2half2(lo[0], lo[1]);
    *(__half2*)(dl + off + 2) = __halves2half2(lo[2], lo[3]);
}

// ---------------------------------------------------------------------------
// q/k/v = x @ W + b via mma.sync; KC=32, 2 stages, 2 CTAs/SM.
// grid (64, 2, 3). z==1 (k) epilogue writes g_kh/g_kl directly.
// ---------------------------------------------------------------------------
#define Q_ITERS   (DD / 32)                 // 8
#define QLDA      40
#define QLDB      136
#define QA_B      (128 * QLDA * 2)          // 10240 per split
#define QB_B      (32 * QLDB * 2)           // 8704 per split
#define QSTAGE_B  (2 * QA_B + 2 * QB_B)     // 37888
#define QNSTAGE   2

__global__ __launch_bounds__(256, 2) void qkvmma_kernel(
    const float* __restrict__ bq, const float* __restrict__ bk,
    const float* __restrict__ bv)
{
    extern __shared__ char smem[];
    const int tid  = threadIdx.x;
    const int wid  = tid >> 5;
    const int lane = tid & 31;
    const int warp_m = wid >> 1;
    const int warp_n = wid & 1;
    const int row0 = blockIdx.x * 128;
    const int n0   = blockIdx.y * 128;
    const int z    = blockIdx.z;
    const __half* Wh = g_wh + (size_t)z * DD * DD;
    const __half* Wl = g_wl + (size_t)z * DD * DD;
    const uint32_t sbase = cvta_smem(smem);

    float acc[2][8][4];
    #pragma unroll
    for (int m = 0; m < 2; m++)
        #pragma unroll
        for (int n = 0; n < 8; n++)
            #pragma unroll
            for (int i = 0; i < 4; i++) acc[m][n][i] = 0.0f;

    #define LOAD_STAGE_Q(st, it)                                                \
    do {                                                                         \
        const int j0 = (it) * 32;                                               \
        const uint32_t sah = sbase + (st) * QSTAGE_B;                           \
        const uint32_t sal = sah + QA_B;                                        \
        const uint32_t sbh = sal + QA_B;                                        \
        const uint32_t sbl = sbh + QB_B;                                        \
        _Pragma("unroll")                                                       \
        for (int u = 0; u < 2; u++) {                                           \
            int c = tid + u * 256;              /* 0..511 */                    \
            int r  = c >> 2;                     /* 0..127 */                   \
            int k8 = (c & 3) * 8;                                               \
            uint32_t off = (uint32_t)(r * QLDA + k8) * 2;                       \
            cp16(sah + off, g_xh + (size_t)(row0 + r) * DD + j0 + k8);          \
            cp16(sal + off, g_xl + (size_t)(row0 + r) * DD + j0 + k8);          \
        }                                                                       \
        _Pragma("unroll")                                                       \
        for (int u = 0; u < 2; u++) {                                           \
            int c = tid + u * 256;                                              \
            int r  = c >> 4;                     /* 0..31 */                    \
            int n8 = (c & 15) * 8;                                              \
            uint32_t off = (uint32_t)(r * QLDB + n8) * 2;                       \
            cp16(sbh + off, Wh + (size_t)(j0 + r) * DD + n0 + n8);              \
            cp16(sbl + off, Wl + (size_t)(j0 + r) * DD + n0 + n8);              \
        }                                                                       \
    } while (0)

    LOAD_STAGE_Q(0, 0); cp_commit();
    LOAD_STAGE_Q(1, 1); cp_commit();

    int buf = 0;
    for (int it = 0; it < Q_ITERS; ++it) {
        cp_wait<1>();
        __syncthreads();
        const uint32_t sah = sbase + buf * QSTAGE_B;
        const uint32_t sal = sah + QA_B;
        const uint32_t sbh = sal + QA_B;
        const uint32_t sbl = sbh + QB_B;

        #pragma unroll
        for (int kk = 0; kk < 2; kk++) {
            uint32_t ah[2][4], al[2][4];
            #pragma unroll
            for (int mf = 0; mf < 2; mf++) {
                int arow = warp_m * 32 + mf * 16 + (lane & 15);
                int acol = kk * 16 + (lane >> 4) * 8;
                uint32_t off = (uint32_t)(arow * QLDA + acol) * 2;
                ldm_x4(sah + off, ah[mf][0], ah[mf][1], ah[mf][2], ah[mf][3]);
                ldm_x4(sal + off, al[mf][0], al[mf][1], al[mf][2], al[mf][3]);
            }
            uint32_t b[8][2];
            #pragma unroll
            for (int nq = 0; nq < 4; nq++) {
                int brow = kk * 16 + (lane & 15);
                int bcol = warp_n * 64 + nq * 16 + (lane >> 4) * 8;
                uint32_t off = (uint32_t)(brow * QLDB + bcol) * 2;
                ldm_x4_t(sbh + off, b[nq*2][0], b[nq*2][1], b[nq*2+1][0], b[nq*2+1][1]);
            }
            #pragma unroll
            for (int mf = 0; mf < 2; mf++)
                #pragma unroll
                for (int nf = 0; nf < 8; nf++) {
                    mma16816(acc[mf][nf], ah[mf], b[nf][0], b[nf][1]);
                    mma16816(acc[mf][nf], al[mf], b[nf][0], b[nf][1]);
                }
            #pragma unroll
            for (int nq = 0; nq < 4; nq++) {
                int brow = kk * 16 + (lane & 15);
                int bcol = warp_n * 64 + nq * 16 + (lane >> 4) * 8;
                uint32_t off = (uint32_t)(brow * QLDB + bcol) * 2;
                ldm_x4_t(sbl + off, b[nq*2][0], b[nq*2][1], b[nq*2+1][0], b[nq*2+1][1]);
            }
            #pragma unroll
            for (int mf = 0; mf < 2; mf++)
                #pragma unroll
                for (int nf = 0; nf < 8; nf++)
                    mma16816(acc[mf][nf], ah[mf], b[nf][0], b[nf][1]);
        }
        __syncthreads();
        if (it + QNSTAGE < Q_ITERS) LOAD_STAGE_Q(buf, it + QNSTAGE);
        cp_commit();
        if (++buf == QNSTAGE) buf = 0;
    }

    const float* bias = (z == 0) ? bq : (z == 1) ? bk : bv;
    #pragma unroll
    for (int mf = 0; mf < 2; mf++) {
        #pragma unroll
        for (int rr = 0; rr < 2; rr++) {
            int row = row0 + warp_m * 32 + mf * 16 + rr * 8 + (lane >> 2);
            #pragma unroll
            for (int nf = 0; nf < 8; nf++) {
                int col = n0 + warp_n * 64 + nf * 8 + (lane & 3) * 2;
                float v0 = acc[mf][nf][rr * 2 + 0] + bias[col];
                float v1 = acc[mf][nf][rr * 2 + 1] + bias[col + 1];
                size_t o = (size_t)row * DD + col;
                if (z == 0) {
                    *(float2*)(g_q + o) = make_float2(v0, v1);
                } else if (z == 2) {
                    *(float2*)(g_v + o) = make_float2(v0, v1);
                } else {
                    __half h0 = __float2half_rn(v0);
                    __half h1 = __float2half_rn(v1);
                    __half l0 = __float2half_rn(v0 - __half2float(h0));
                    __half l1 = __float2half_rn(v1 - __half2float(h1));
                    *(__half2*)(g_kh + o) = __halves2half2(h0, h1);
                    *(__half2*)(g_kl + o) = __halves2half2(l0, l1);
                }
            }
        }
    }
}

// ---------------------------------------------------------------------------
// s partials via fp16 mma.sync. ONE barrier per iteration:
//   A32 raw adj: 2 buffers (written iter i, converted iter i+1)
//   B (kh/kl):   3-slot ring (written iter i for stage i+2, read iter i+2)
//   A16 fp16:    2 buffers (convert of stage i+1 overlaps MMA of stage i)
// Iter i: cp_wait<0>; sync; convert(i+1); MMA(i); LOAD(i+2); commit.
// Grid (64, 2, 2), 256 threads, 2 CTAs/SM, KC=32, 2m x 4n warps.
// ---------------------------------------------------------------------------
#define S_ITERS   (NN / 2 / 32)             // 128
#define SLDA      40                         // fp16 A buffer stride (halfs)
#define SLDB      136
#define SA32_B    (128 * 32 * 4)            // 16384 per A32 buffer
#define SB_B      (32 * SLDB * 2)           // 8704 per split
#define SBSTAGE_B (2 * SB_B)                // 17408 per B slot
#define B_OFF     (2 * SA32_B)              // 32768
#define A16_OFF   (B_OFF + 3 * SBSTAGE_B)   // 84992
#define A16_B     (128 * SLDA * 2)          // 10240 per A16 buffer
#define S_SMEM    (A16_OFF + 2 * A16_B)     // 105472

__global__ __launch_bounds__(256, 2) void smma_kernel(const float* __restrict__ adj)
{
    extern __shared__ char smem[];

    const int tid  = threadIdx.x;
    const int wid  = tid >> 5;
    const int lane = tid & 31;
    const int warp_m = wid >> 2;      // 0..1 (64 rows each)
    const int warp_n = wid & 3;       // 0..3 (32 cols each)
    const int row0 = blockIdx.x * 128;
    const int n0   = blockIdx.y * 128;
    const int kbase = blockIdx.z * (NN / 2);
    const uint32_t sbase = cvta_smem(smem);

    float acc[4][4][4];
    #pragma unroll
    for (int m = 0; m < 4; m++)
        #pragma unroll
        for (int n = 0; n < 4; n++)
            #pragma unroll
            for (int i = 0; i < 4; i++) acc[m][n][i] = 0.0f;

    // load stage `it`: A32 buffer it%2, B slot it%3
    #define LOAD_STAGE_S(it)                                                     \
    do {                                                                         \
        const int j0 = kbase + (it) * 32;                                       \
        const uint32_t sa32 = sbase + ((it) & 1) * SA32_B;                      \
        const uint32_t sh = sbase + B_OFF + ((it) % 3) * SBSTAGE_B;             \
        const uint32_t sl = sh + SB_B;                                          \
        _Pragma("unroll")                                                       \
        for (int u = 0; u < 4; u++) {                                           \
            int c = tid + u * 256;              /* 0..1023 */                   \
            int r  = c >> 3;                     /* 0..127 */                   \
            int k4 = (c & 7) * 4;                                               \
            cp16(sa32 + (uint32_t)(r * 32 + k4) * 4,                            \
                 adj + (size_t)(row0 + r) * NN + j0 + k4);                      \
        }                                                                       \
        _Pragma("unroll")                                                       \
        for (int u = 0; u < 2; u++) {                                           \
            int c = tid + u * 256;                                              \
            int r  = c >> 4;                     /* 0..31 */                    \
            int n8 = (c & 15) * 8;                                              \
            uint32_t off = (uint32_t)(r * SLDB + n8) * 2;                       \
            cp16(sh + off, g_kh + (size_t)(j0 + r) * DD + n0 + n8);             \
            cp16(sl + off, g_kl + (size_t)(j0 + r) * DD + n0 + n8);             \
        }                                                                       \
    } while (0)

    // convert A32 buffer (st&1) -> A16 buffer (st&1)
    #define CONVERT_S(st)                                                        \
    do {                                                                         \
        const char* a32p = smem + (size_t)((st) & 1) * SA32_B;                  \
        char* a16p = smem + A16_OFF + (size_t)((st) & 1) * A16_B;               \
        _Pragma("unroll")                                                       \
        for (int u = 0; u < 4; u++) {                                           \
            int c = tid + u * 256;                                              \
            int r  = c >> 3;                                                    \
            int k4 = (c & 7) * 4;                                               \
            float4 v = *(const float4*)(a32p + (size_t)(r * 32 + k4) * 4);      \
            __half2 h01 = __floats2half2_rn(v.x, v.y);                          \
            __half2 h23 = __floats2half2_rn(v.z, v.w);                          \
            char* dst = a16p + (size_t)(r * SLDA + k4) * 2;                     \
            *(__half2*)(dst)     = h01;                                         \
            *(__half2*)(dst + 4) = h23;                                         \
        }                                                                       \
    } while (0)

    // prologue: load stages 0,1; convert stage 0
    LOAD_STAGE_S(0); cp_commit();
    LOAD_STAGE_S(1); cp_commit();
    cp_wait<1>();                 // stage 0 complete
    __syncthreads();
    CONVERT_S(0);

    for (int it = 0; it < S_ITERS; ++it) {
        cp_wait<0>();             // all loaded stages complete (<= it+1)
        __syncthreads();          // A16(it) visible; prior MMA reads done

        if (it + 1 < S_ITERS) CONVERT_S(it + 1);   // overlaps MMA(it)

        const uint32_t a16 = sbase + A16_OFF + (uint32_t)(it & 1) * A16_B;
        const uint32_t sh  = sbase + B_OFF + (uint32_t)(it % 3) * SBSTAGE_B;
        const uint32_t sl  = sh + SB_B;

        #pragma unroll
        for (int kk = 0; kk < 2; kk++) {
            uint32_t a[4][4];
            #pragma unroll
            for (int mf = 0; mf < 4; mf++) {
                int arow = warp_m * 64 + mf * 16 + (lane & 15);
                int acol = kk * 16 + (lane >> 4) * 8;
                ldm_x4(a16 + (uint32_t)(arow * SLDA + acol) * 2,
                       a[mf][0], a[mf][1], a[mf][2], a[mf][3]);
            }
            uint32_t b[4][2];
            #pragma unroll
            for (int ng = 0; ng < 2; ng++) {
                int brow = kk * 16 + (lane & 15);
                int bcol = warp_n * 32 + ng * 16 + (lane >> 4) * 8;
                uint32_t off = (uint32_t)(brow * SLDB + bcol) * 2;
                ldm_x4_t(sh + off, b[ng*2][0], b[ng*2][1], b[ng*2+1][0], b[ng*2+1][1]);
            }
            #pragma unroll
            for (int mf = 0; mf < 4; mf++)
                #pragma unroll
                for (int nf = 0; nf < 4; nf++)
                    mma16816(acc[mf][nf], a[mf], b[nf][0], b[nf][1]);
            #pragma unroll
            for (int ng = 0; ng < 2; ng++) {
                int brow = kk * 16 + (lane & 15);
                int bcol = warp_n * 32 + ng * 16 + (lane >> 4) * 8;
                uint32_t off = (uint32_t)(brow * SLDB + bcol) * 2;
                ldm_x4_t(sl + off, b[ng*2][0], b[ng*2][1], b[ng*2+1][0], b[ng*2+1][1]);
            }
            #pragma unroll
            for (int mf = 0; mf < 4; mf++)
                #pragma unroll
                for (int nf = 0; nf < 4; nf++)
                    mma16816(acc[mf][nf], a[mf], b[nf][0], b[nf][1]);
        }

        if (it + 2 < S_ITERS) LOAD_STAGE_S(it + 2);
        cp_commit();
    }

    // fused epilogue: p[row] = sum_n m[row][n] * q[row][n0+n]
    // srow scratch reuses the A16 region (free after mainloop).
    __syncthreads();
    float* srow = (float*)(smem + A16_OFF);
    #pragma unroll
    for (int mf = 0; mf < 4; mf++) {
        #pragma unroll
        for (int rr = 0; rr < 2; rr++) {
            int lrow = warp_m * 64 + mf * 16 + rr * 8 + (lane >> 2);
            int grow = row0 + lrow;
            float p = 0.0f;
            #pragma unroll
            for (int nf = 0; nf < 4; nf++) {
                int gcol = n0 + warp_n * 32 + nf * 8 + (lane & 3) * 2;
                float2 qq = *(const float2*)(g_q + (size_t)grow * DD + gcol);
                p += acc[mf][nf][rr * 2 + 0] * qq.x
                   + acc[mf][nf][rr * 2 + 1] * qq.y;
            }
            p += __shfl_xor_sync(0xffffffffu, p, 1);
            p += __shfl_xor_sync(0xffffffffu, p, 2);
            if ((lane & 3) == 0) srow[warp_n * 128 + lrow] = p;
        }
    }
    __syncthreads();
    if (tid < 128)
        g_spart[(size_t)(blockIdx.y * 2 + blockIdx.z) * NN + row0 + tid] =
            srow[0 * 128 + tid] + srow[1 * 128 + tid] +
            srow[2 * 128 + tid] + srow[3 * 128 + tid];
}

// ---------------------------------------------------------------------------
// softmax: combine 4 partials, max, exp, sum; store exp() in g_alpha,
// 1/sum in g_inv. Normalization folded into out_kernel.
// ---------------------------------------------------------------------------
__global__ __launch_bounds__(1024) void softmax_kernel()
{
    __shared__ float red[32];
    const int tid = threadIdx.x;
    const int lane = tid & 31;
    const int wid = tid >> 5;

    float sv[8];
    float lmax = -3.4e38f;
    #pragma unroll
    for (int u = 0; u < 8; u++) {
        int i = tid + u * 1024;
        float s = g_spart[i] + g_spart[NN + i] + g_spart[2 * NN + i] + g_spart[3 * NN + i];
        sv[u] = s;
        lmax = fmaxf(lmax, s);
    }
    #pragma unroll
    for (int off = 16; off > 0; off >>= 1)
        lmax = fmaxf(lmax, __shfl_xor_sync(0xffffffffu, lmax, off));
    if (lane == 0) red[wid] = lmax;
    __syncthreads();
    float m = red[lane];
    #pragma unroll
    for (int off = 16; off > 0; off >>= 1)
        m = fmaxf(m, __shfl_xor_sync(0xffffffffu, m, off));
    __syncthreads();

    float lsum = 0.0f;
    #pragma unroll
    for (int u = 0; u < 8; u++) {
        int i = tid + u * 1024;
        float e = expf(sv[u] - m);
        g_alpha[i] = e;
        lsum += e;
    }
    #pragma unroll
    for (int off = 16; off > 0; off >>= 1)
        lsum += __shfl_xor_sync(0xffffffffu, lsum, off);
    if (lane == 0) red[wid] = lsum;
    __syncthreads();
    float ssum = red[lane];
    #pragma unroll
    for (int off = 16; off > 0; off >>= 1)
        ssum += __shfl_xor_sync(0xffffffffu, ssum, off);
    if (tid == 0) g_inv = 1.0f / ssum;
}

// ---------------------------------------------------------------------------
// out[i, :] = (alpha_exp[i] * inv) * v[i, :]; + normalized alpha tail.
// ---------------------------------------------------------------------------
__global__ __launch_bounds__(256) void out_kernel(float* __restrict__ out,
                                                  int write_tail)
{
    const int total4 = NN * DD / 4;
    int idx = blockIdx.x * blockDim.x + threadIdx.x;
    float inv = g_inv;
    if (idx < total4) {
        int row = (idx * 4) / DD;
        float a = g_alpha[row] * inv;
        float4 v4 = *(const float4*)(g_v + (size_t)idx * 4);
        v4.x *= a; v4.y *= a; v4.z *= a; v4.w *= a;
        *(float4*)(out + (size_t)idx * 4) = v4;
    } else if (idx < total4 + NN / 4) {
        if (write_tail) {
            int j = (idx - total4) * 4;
            float4 a4 = *(const float4*)(g_alpha + j);
            a4.x *= inv; a4.y *= inv; a4.z *= inv; a4.w *= inv;
            *(float4*)(out + (size_t)NN * DD + j) = a4;
        }
    }
}

// ---------------------------------------------------------------------------
extern "C" void kernel_launch(void* const* d_in, const int* in_sizes, int n_in,
                              void* d_out, int out_size) {
    const float* x   = (const float*)d_in[0];
    const float* adj = (const float*)d_in[1];
    const float* Wq  = (const float*)d_in[2];
    const float* bq  = (const float*)d_in[3];
    const float* Wk  = (const float*)d_in[4];
    const float* bk  = (const float*)d_in[5];
    const float* Wv  = (const float*)d_in[6];
    const float* bv  = (const float*)d_in[7];
    float* out = (float*)d_out;

    // x + W -> fp16 hi/lo (fused)
    {
        int total = NN * DD / 4 + 3 * DD * DD / 4;
        split_kernel<<<(total + 255) / 256, 256>>>(x, Wq, Wk, Wv);
    }

    // q/k/v projections via mma (k written directly as hi/lo splits)
    cudaFuncSetAttribute(qkvmma_kernel, cudaFuncAttributeMaxDynamicSharedMemorySize,
                         QNSTAGE * QSTAGE_B);
    dim3 gq(NN / 128, 2, 3);
    qkvmma_kernel<<<gq, 256, QNSTAGE * QSTAGE_B>>>(bq, bk, bv);

    // s partials: raw fp32 adj via cp.async, software-pipelined in-kernel
    // convert (A16 double buffer), one barrier per iteration
    cudaFuncSetAttribute(smma_kernel, cudaFuncAttributeMaxDynamicSharedMemorySize,
                         S_SMEM);
    dim3 gs(NN / 128, 2, 2);
    smma_kernel<<<gs, 256, S_SMEM>>>(adj);

    // softmax (exp + 1/sum only; normalization fused into out_kernel)
    softmax_kernel<<<1, 1024>>>();

    // out = alpha[:,None] * v  (+ normalized alpha tail)
    int write_tail = (out_size >= NN * DD + NN) ? 1 : 0;
    int total = NN * DD / 4 + NN / 4;
    out_kernel<<<(total + 255) / 256, 256>>>(out, write_tail);
}

// round 15
// speedup vs baseline: 1.1463x; 1.1463x over previous
#include <cuda_runtime.h>
#include <cuda_fp16.h>
#include <cstdint>

#define NN 8192
#define DD 256

// ---------------- scratch (device globals; no allocation allowed) ----------
__device__ float  g_q[NN * DD];
__device__ float  g_v[NN * DD];
__device__ __half g_xh[NN * DD];              // x hi split
__device__ __half g_xl[NN * DD];              // x lo split
__device__ __half g_wh[3 * DD * DD];          // Wq|Wk|Wv hi split
__device__ __half g_wl[3 * DD * DD];          // Wq|Wk|Wv lo split
__device__ __half g_kh[NN * DD];              // k hi split [j][d]
__device__ __half g_kl[NN * DD];              // k lo split
__device__ float  g_spart[4 * NN];            // deterministic partials
__device__ float  g_alpha[NN];                // exp(s - max) (unnormalized)
__device__ float  g_inv;                      // 1 / sum(exp)

// ---------------- PTX helpers (base sm_80+ ISA only) ------------------------
__device__ __forceinline__ uint32_t cvta_smem(const void* p) {
    uint32_t a;
    asm("{ .reg .u64 t; cvta.to.shared.u64 t, %1; cvt.u32.u64 %0, t; }"
        : "=r"(a) : "l"(p));
    return a;
}
__device__ __forceinline__ void cp16(uint32_t dst, const void* src) {
    asm volatile("cp.async.cg.shared.global [%0], [%1], 16;" :: "r"(dst), "l"(src));
}
__device__ __forceinline__ void cp_commit() {
    asm volatile("cp.async.commit_group;" ::: "memory");
}
template <int N>
__device__ __forceinline__ void cp_wait() {
    asm volatile("cp.async.wait_group %0;" :: "n"(N) : "memory");
}
__device__ __forceinline__ void ldm_x4(uint32_t addr, uint32_t& r0, uint32_t& r1,
                                       uint32_t& r2, uint32_t& r3) {
    asm volatile("ldmatrix.sync.aligned.m8n8.x4.shared.b16 {%0,%1,%2,%3}, [%4];"
                 : "=r"(r0), "=r"(r1), "=r"(r2), "=r"(r3) : "r"(addr));
}
__device__ __forceinline__ void ldm_x4_t(uint32_t addr, uint32_t& r0, uint32_t& r1,
                                         uint32_t& r2, uint32_t& r3) {
    asm volatile("ldmatrix.sync.aligned.m8n8.x4.trans.shared.b16 {%0,%1,%2,%3}, [%4];"
                 : "=r"(r0), "=r"(r1), "=r"(r2), "=r"(r3) : "r"(addr));
}
__device__ __forceinline__ void mma16816(float* c, const uint32_t* a,
                                         uint32_t b0, uint32_t b1) {
    asm volatile(
        "mma.sync.aligned.m16n8k16.row.col.f32.f16.f16.f32 "
        "{%0,%1,%2,%3}, {%4,%5,%6,%7}, {%8,%9}, {%0,%1,%2,%3};"
        : "+f"(c[0]), "+f"(c[1]), "+f"(c[2]), "+f"(c[3])
        : "r"(a[0]), "r"(a[1]), "r"(a[2]), "r"(a[3]), "r"(b0), "r"(b1));
}

// ---------------------------------------------------------------------------
// fused x-split + W-split
// ---------------------------------------------------------------------------
__global__ __launch_bounds__(256) void split_kernel(const float* __restrict__ x,
                                                    const float* __restrict__ Wq,
                                                    const float* __restrict__ Wk,
                                                    const float* __restrict__ Wv)
{
    const int X4 = NN * DD / 4;
    const int W4 = DD * DD / 4;
    int i4 = blockIdx.x * blockDim.x + threadIdx.x;
    const float* src;
    __half *dh, *dl;
    size_t off;
    if (i4 < X4) {
        src = x; dh = g_xh; dl = g_xl; off = (size_t)i4 * 4;
    } else if (i4 < X4 + 3 * W4) {
        int r = i4 - X4;
        int z = r / W4;
        int w = r - z * W4;
        src = (z == 0) ? Wq : (z == 1) ? Wk : Wv;
        dh = g_wh + (size_t)z * DD * DD;
        dl = g_wl + (size_t)z * DD * DD;
        off = (size_t)w * 4;
    } else {
        return;
    }
    float4 v4 = *(const float4*)(src + off);
    float vs[4] = {v4.x, v4.y, v4.z, v4.w};
    __half hi[4], lo[4];
    #pragma unroll
    for (int i = 0; i < 4; i++) {
        hi[i] = __float2half_rn(vs[i]);
        lo[i] = __float2half_rn(vs[i] - __half2float(hi[i]));
    }
    *(__half2*)(dh + off)     = __halves2half2(hi[0], hi[1]);
    *(__half2*)(dh + off + 2) = __halves2half2(hi[2], hi[3]);
    *(__half2*)(dl + off)     = __halves2half2(lo[0], lo[1]);
    *(__half2*)(dl + off + 2) = __halves2half2(lo[2], lo[3]);
}

// ---------------------------------------------------------------------------
// q/k/v = x @ W + b via mma.sync; KC=32, 2 stages, 2 CTAs/SM.
// grid (64, 2, 3). z==1 (k) epilogue writes g_kh/g_kl directly.
// ---------------------------------------------------------------------------
#define Q_ITERS   (DD / 32)                 // 8
#define QLDA      40
#define QLDB      136
#define QA_B      (128 * QLDA * 2)          // 10240 per split
#define QB_B      (32 * QLDB * 2)           // 8704 per split
#define QSTAGE_B  (2 * QA_B + 2 * QB_B)     // 37888
#define QNSTAGE   2

__global__ __launch_bounds__(256, 2) void qkvmma_kernel(
    const float* __restrict__ bq, const float* __restrict__ bk,
    const float* __restrict__ bv)
{
    extern __shared__ char smem[];
    const int tid  = threadIdx.x;
    const int wid  = tid >> 5;
    const int lane = tid & 31;
    const int warp_m = wid >> 1;
    const int warp_n = wid & 1;
    const int row0 = blockIdx.x * 128;
    const int n0   = blockIdx.y * 128;
    const int z    = blockIdx.z;
    const __half* Wh = g_wh + (size_t)z * DD * DD;
    const __half* Wl = g_wl + (size_t)z * DD * DD;
    const uint32_t sbase = cvta_smem(smem);

    float acc[2][8][4];
    #pragma unroll
    for (int m = 0; m < 2; m++)
        #pragma unroll
        for (int n = 0; n < 8; n++)
            #pragma unroll
            for (int i = 0; i < 4; i++) acc[m][n][i] = 0.0f;

    #define LOAD_STAGE_Q(st, it)                                                \
    do {                                                                         \
        const int j0 = (it) * 32;                                               \
        const uint32_t sah = sbase + (st) * QSTAGE_B;                           \
        const uint32_t sal = sah + QA_B;                                        \
        const uint32_t sbh = sal + QA_B;                                        \
        const uint32_t sbl = sbh + QB_B;                                        \
        _Pragma("unroll")                                                       \
        for (int u = 0; u < 2; u++) {                                           \
            int c = tid + u * 256;              /* 0..511 */                    \
            int r  = c >> 2;                     /* 0..127 */                   \
            int k8 = (c & 3) * 8;                                               \
            uint32_t off = (uint32_t)(r * QLDA + k8) * 2;                       \
            cp16(sah + off, g_xh + (size_t)(row0 + r) * DD + j0 + k8);          \
            cp16(sal + off, g_xl + (size_t)(row0 + r) * DD + j0 + k8);          \
        }                                                                       \
        _Pragma("unroll")                                                       \
        for (int u = 0; u < 2; u++) {                                           \
            int c = tid + u * 256;                                              \
            int r  = c >> 4;                     /* 0..31 */                    \
            int n8 = (c & 15) * 8;                                              \
            uint32_t off = (uint32_t)(r * QLDB + n8) * 2;                       \
            cp16(sbh + off, Wh + (size_t)(j0 + r) * DD + n0 + n8);              \
            cp16(sbl + off, Wl + (size_t)(j0 + r) * DD + n0 + n8);              \
        }                                                                       \
    } while (0)

    LOAD_STAGE_Q(0, 0); cp_commit();
    LOAD_STAGE_Q(1, 1); cp_commit();

    int buf = 0;
    for (int it = 0; it < Q_ITERS; ++it) {
        cp_wait<1>();
        __syncthreads();
        const uint32_t sah = sbase + buf * QSTAGE_B;
        const uint32_t sal = sah + QA_B;
        const uint32_t sbh = sal + QA_B;
        const uint32_t sbl = sbh + QB_B;

        #pragma unroll
        for (int kk = 0; kk < 2; kk++) {
            uint32_t ah[2][4], al[2][4];
            #pragma unroll
            for (int mf = 0; mf < 2; mf++) {
                int arow = warp_m * 32 + mf * 16 + (lane & 15);
                int acol = kk * 16 + (lane >> 4) * 8;
                uint32_t off = (uint32_t)(arow * QLDA + acol) * 2;
                ldm_x4(sah + off, ah[mf][0], ah[mf][1], ah[mf][2], ah[mf][3]);
                ldm_x4(sal + off, al[mf][0], al[mf][1], al[mf][2], al[mf][3]);
            }
            uint32_t b[8][2];
            #pragma unroll
            for (int nq = 0; nq < 4; nq++) {
                int brow = kk * 16 + (lane & 15);
                int bcol = warp_n * 64 + nq * 16 + (lane >> 4) * 8;
                uint32_t off = (uint32_t)(brow * QLDB + bcol) * 2;
                ldm_x4_t(sbh + off, b[nq*2][0], b[nq*2][1], b[nq*2+1][0], b[nq*2+1][1]);
            }
            #pragma unroll
            for (int mf = 0; mf < 2; mf++)
                #pragma unroll
                for (int nf = 0; nf < 8; nf++) {
                    mma16816(acc[mf][nf], ah[mf], b[nf][0], b[nf][1]);
                    mma16816(acc[mf][nf], al[mf], b[nf][0], b[nf][1]);
                }
            #pragma unroll
            for (int nq = 0; nq < 4; nq++) {
                int brow = kk * 16 + (lane & 15);
                int bcol = warp_n * 64 + nq * 16 + (lane >> 4) * 8;
                uint32_t off = (uint32_t)(brow * QLDB + bcol) * 2;
                ldm_x4_t(sbl + off, b[nq*2][0], b[nq*2][1], b[nq*2+1][0], b[nq*2+1][1]);
            }
            #pragma unroll
            for (int mf = 0; mf < 2; mf++)
                #pragma unroll
                for (int nf = 0; nf < 8; nf++)
                    mma16816(acc[mf][nf], ah[mf], b[nf][0], b[nf][1]);
        }
        __syncthreads();
        if (it + QNSTAGE < Q_ITERS) LOAD_STAGE_Q(buf, it + QNSTAGE);
        cp_commit();
        if (++buf == QNSTAGE) buf = 0;
    }

    const float* bias = (z == 0) ? bq : (z == 1) ? bk : bv;
    #pragma unroll
    for (int mf = 0; mf < 2; mf++) {
        #pragma unroll
        for (int rr = 0; rr < 2; rr++) {
            int row = row0 + warp_m * 32 + mf * 16 + rr * 8 + (lane >> 2);
            #pragma unroll
            for (int nf = 0; nf < 8; nf++) {
                int col = n0 + warp_n * 64 + nf * 8 + (lane & 3) * 2;
                float v0 = acc[mf][nf][rr * 2 + 0] + bias[col];
                float v1 = acc[mf][nf][rr * 2 + 1] + bias[col + 1];
                size_t o = (size_t)row * DD + col;
                if (z == 0) {
                    *(float2*)(g_q + o) = make_float2(v0, v1);
                } else if (z == 2) {
                    *(float2*)(g_v + o) = make_float2(v0, v1);
                } else {
                    __half h0 = __float2half_rn(v0);
                    __half h1 = __float2half_rn(v1);
                    __half l0 = __float2half_rn(v0 - __half2float(h0));
                    __half l1 = __float2half_rn(v1 - __half2float(h1));
                    *(__half2*)(g_kh + o) = __halves2half2(h0, h1);
                    *(__half2*)(g_kl + o) = __halves2half2(l0, l1);
                }
            }
        }
    }
}

// ---------------------------------------------------------------------------
// s partials via fp16 mma.sync; raw fp32 adj cp.async'd + in-pipeline convert.
// ROUND-13 pipeline restored (measured best): cp_wait<1>; sync; load(i+2);
// commit; convert(i); sync; mma(i).
// NEW (only change): the post-convert barrier is a 128-thread NAMED barrier
// per warp_m group — each half converts and reads only its own 64 A16 rows,
// so block-wide ordering is unnecessary there.
// Grid (64, 2, 2), 256 threads, 2 CTAs/SM, KC=32, 3-stage ring, 2m x 4n warps.
// ---------------------------------------------------------------------------
#define S_ITERS   (NN / 2 / 32)             // 128
#define SLDA      40                         // fp16 A buffer stride (halfs)
#define SLDB      136
#define SA32_B    (128 * 32 * 4)            // 16384 (raw fp32 adj tile)
#define SB_B      (32 * SLDB * 2)           // 8704
#define SSTAGE_B  (SA32_B + 2 * SB_B)       // 33792
#define SNSTAGE   3
#define A16_OFF   (SNSTAGE * SSTAGE_B)      // 101376
#define A16_B     (128 * SLDA * 2)          // 10240
#define S_SMEM    (A16_OFF + A16_B)         // 111616

__global__ __launch_bounds__(256, 2) void smma_kernel(const float* __restrict__ adj)
{
    extern __shared__ char smem[];

    const int tid  = threadIdx.x;
    const int wid  = tid >> 5;
    const int lane = tid & 31;
    const int warp_m = wid >> 2;      // 0..1 (64 rows each)
    const int warp_n = wid & 3;       // 0..3 (32 cols each)
    const int row0 = blockIdx.x * 128;
    const int n0   = blockIdx.y * 128;
    const int kbase = blockIdx.z * (NN / 2);
    const uint32_t sbase = cvta_smem(smem);
    const uint32_t a16   = sbase + A16_OFF;
    const int grp  = warp_m;          // 0 or 1 (tids 0-127 / 128-255)
    const int wg   = tid & 127;       // index within half

    float acc[4][4][4];
    #pragma unroll
    for (int m = 0; m < 4; m++)
        #pragma unroll
        for (int n = 0; n < 4; n++)
            #pragma unroll
            for (int i = 0; i < 4; i++) acc[m][n][i] = 0.0f;

    #define LOAD_STAGE_S(st, it)                                                \
    do {                                                                         \
        const int j0 = kbase + (it) * 32;                                       \
        const uint32_t sa32 = sbase + (st) * SSTAGE_B;                          \
        const uint32_t sh = sa32 + SA32_B;                                      \
        const uint32_t sl = sh + SB_B;                                          \
        _Pragma("unroll")                                                       \
        for (int u = 0; u < 4; u++) {                                           \
            int c = tid + u * 256;              /* 0..1023 */                   \
            int r  = c >> 3;                     /* 0..127 */                   \
            int k4 = (c & 7) * 4;                                               \
            cp16(sa32 + (uint32_t)(r * 32 + k4) * 4,                            \
                 adj + (size_t)(row0 + r) * NN + j0 + k4);                      \
        }                                                                       \
        _Pragma("unroll")                                                       \
        for (int u = 0; u < 2; u++) {                                           \
            int c = tid + u * 256;                                              \
            int r  = c >> 4;                     /* 0..31 */                    \
            int n8 = (c & 15) * 8;                                              \
            uint32_t off = (uint32_t)(r * SLDB + n8) * 2;                       \
            cp16(sh + off, g_kh + (size_t)(j0 + r) * DD + n0 + n8);             \
            cp16(sl + off, g_kl + (size_t)(j0 + r) * DD + n0 + n8);             \
        }                                                                       \
    } while (0)

    LOAD_STAGE_S(0, 0); cp_commit();
    LOAD_STAGE_S(1, 1); cp_commit();

    int buf = 0;       // it % 3
    int nxt = 2;       // (it+2) % 3
    for (int it = 0; it < S_ITERS; ++it) {
        cp_wait<1>();
        __syncthreads();        // stage `buf` data ready; stage `nxt` buffer free

        // prefetch stage it+2 into the buffer consumed at it-1
        if (it + 2 < S_ITERS) LOAD_STAGE_S(nxt, it + 2);
        cp_commit();

        const uint32_t sa32 = sbase + buf * SSTAGE_B;
        const uint32_t sh = sa32 + SA32_B;
        const uint32_t sl = sh + SB_B;

        // convert fp32 adj tile -> fp16 A buffer: each 128-thread half
        // converts ONLY its own 64 rows (the rows its warps will ldmatrix).
        {
            const char* a32p = smem + (size_t)buf * SSTAGE_B;
            #pragma unroll
            for (int u = 0; u < 4; u++) {
                int c = wg + u * 128;            // 0..511 within half
                int r  = grp * 64 + (c >> 3);    // this half's rows
                int k4 = (c & 7) * 4;
                float4 v = *(const float4*)(a32p + (size_t)(r * 32 + k4) * 4);
                __half2 h01 = __floats2half2_rn(v.x, v.y);
                __half2 h23 = __floats2half2_rn(v.z, v.w);
                char* dst = smem + A16_OFF + (size_t)(r * SLDA + k4) * 2;
                *(__half2*)(dst)     = h01;
                *(__half2*)(dst + 4) = h23;
            }
        }
        // half-scope ordering: A16 rows of this half visible to its 4 warps
        asm volatile("bar.sync %0, 128;" :: "r"(1 + grp) : "memory");

        #pragma unroll
        for (int kk = 0; kk < 2; kk++) {
            uint32_t a[4][4];
            #pragma unroll
            for (int mf = 0; mf < 4; mf++) {
                int arow = warp_m * 64 + mf * 16 + (lane & 15);
                int acol = kk * 16 + (lane >> 4) * 8;
                ldm_x4(a16 + (uint32_t)(arow * SLDA + acol) * 2,
                       a[mf][0], a[mf][1], a[mf][2], a[mf][3]);
            }
            uint32_t b[4][2];
            #pragma unroll
            for (int ng = 0; ng < 2; ng++) {
                int brow = kk * 16 + (lane & 15);
                int bcol = warp_n * 32 + ng * 16 + (lane >> 4) * 8;
                uint32_t off = (uint32_t)(brow * SLDB + bcol) * 2;
                ldm_x4_t(sh + off, b[ng*2][0], b[ng*2][1], b[ng*2+1][0], b[ng*2+1][1]);
            }
            #pragma unroll
            for (int mf = 0; mf < 4; mf++)
                #pragma unroll
                for (int nf = 0; nf < 4; nf++)
                    mma16816(acc[mf][nf], a[mf], b[nf][0], b[nf][1]);
            #pragma unroll
            for (int ng = 0; ng < 2; ng++) {
                int brow = kk * 16 + (lane & 15);
                int bcol = warp_n * 32 + ng * 16 + (lane >> 4) * 8;
                uint32_t off = (uint32_t)(brow * SLDB + bcol) * 2;
                ldm_x4_t(sl + off, b[ng*2][0], b[ng*2][1], b[ng*2+1][0], b[ng*2+1][1]);
            }
            #pragma unroll
            for (int mf = 0; mf < 4; mf++)
                #pragma unroll
                for (int nf = 0; nf < 4; nf++)
                    mma16816(acc[mf][nf], a[mf], b[nf][0], b[nf][1]);
        }

        buf = (buf == 2) ? 0 : buf + 1;
        nxt = (nxt == 2) ? 0 : nxt + 1;
    }

    // fused epilogue: p[row] = sum_n m[row][n] * q[row][n0+n]
    // srow scratch reuses the A16 buffer region (free after mainloop).
    __syncthreads();
    float* srow = (float*)(smem + A16_OFF);
    #pragma unroll
    for (int mf = 0; mf < 4; mf++) {
        #pragma unroll
        for (int rr = 0; rr < 2; rr++) {
            int lrow = warp_m * 64 + mf * 16 + rr * 8 + (lane >> 2);
            int grow = row0 + lrow;
            float p = 0.0f;
            #pragma unroll
            for (int nf = 0; nf < 4; nf++) {
                int gcol = n0 + warp_n * 32 + nf * 8 + (lane & 3) * 2;
                float2 qq = *(const float2*)(g_q + (size_t)grow * DD + gcol);
                p += acc[mf][nf][rr * 2 + 0] * qq.x
                   + acc[mf][nf][rr * 2 + 1] * qq.y;
            }
            p += __shfl_xor_sync(0xffffffffu, p, 1);
            p += __shfl_xor_sync(0xffffffffu, p, 2);
            if ((lane & 3) == 0) srow[warp_n * 128 + lrow] = p;
        }
    }
    __syncthreads();
    if (tid < 128)
        g_spart[(size_t)(blockIdx.y * 2 + blockIdx.z) * NN + row0 + tid] =
            srow[0 * 128 + tid] + srow[1 * 128 + tid] +
            srow[2 * 128 + tid] + srow[3 * 128 + tid];
}

// ---------------------------------------------------------------------------
// softmax: combine 4 partials, max, exp, sum; store exp() in g_alpha,
// 1/sum in g_inv. Normalization folded into out_kernel.
// ---------------------------------------------------------------------------
__global__ __launch_bounds__(1024) void softmax_kernel()
{
    __shared__ float red[32];
    const int tid = threadIdx.x;
    const int lane = tid & 31;
    const int wid = tid >> 5;

    float sv[8];
    float lmax = -3.4e38f;
    #pragma unroll
    for (int u = 0; u < 8; u++) {
        int i = tid + u * 1024;
        float s = g_spart[i] + g_spart[NN + i] + g_spart[2 * NN + i] + g_spart[3 * NN + i];
        sv[u] = s;
        lmax = fmaxf(lmax, s);
    }
    #pragma unroll
    for (int off = 16; off > 0; off >>= 1)
        lmax = fmaxf(lmax, __shfl_xor_sync(0xffffffffu, lmax, off));
    if (lane == 0) red[wid] = lmax;
    __syncthreads();
    float m = red[lane];
    #pragma unroll
    for (int off = 16; off > 0; off >>= 1)
        m = fmaxf(m, __shfl_xor_sync(0xffffffffu, m, off));
    __syncthreads();

    float lsum = 0.0f;
    #pragma unroll
    for (int u = 0; u < 8; u++) {
        int i = tid + u * 1024;
        float e = expf(sv[u] - m);
        g_alpha[i] = e;
        lsum += e;
    }
    #pragma unroll
    for (int off = 16; off > 0; off >>= 1)
        lsum += __shfl_xor_sync(0xffffffffu, lsum, off);
    if (lane == 0) red[wid] = lsum;
    __syncthreads();
    float ssum = red[lane];
    #pragma unroll
    for (int off = 16; off > 0; off >>= 1)
        ssum += __shfl_xor_sync(0xffffffffu, ssum, off);
    if (tid == 0) g_inv = 1.0f / ssum;
}

// ---------------------------------------------------------------------------
// out[i, :] = (alpha_exp[i] * inv) * v[i, :]; + normalized alpha tail.
// ---------------------------------------------------------------------------
__global__ __launch_bounds__(256) void out_kernel(float* __restrict__ out,
                                                  int write_tail)
{
    const int total4 = NN * DD / 4;
    int idx = blockIdx.x * blockDim.x + threadIdx.x;
    float inv = g_inv;
    if (idx < total4) {
        int row = (idx * 4) / DD;
        float a = g_alpha[row] * inv;
        float4 v4 = *(const float4*)(g_v + (size_t)idx * 4);
        v4.x *= a; v4.y *= a; v4.z *= a; v4.w *= a;
        *(float4*)(out + (size_t)idx * 4) = v4;
    } else if (idx < total4 + NN / 4) {
        if (write_tail) {
            int j = (idx - total4) * 4;
            float4 a4 = *(const float4*)(g_alpha + j);
            a4.x *= inv; a4.y *= inv; a4.z *= inv; a4.w *= inv;
            *(float4*)(out + (size_t)NN * DD + j) = a4;
        }
    }
}

// ---------------------------------------------------------------------------
extern "C" void kernel_launch(void* const* d_in, const int* in_sizes, int n_in,
                              void* d_out, int out_size) {
    const float* x   = (const float*)d_in[0];
    const float* adj = (const float*)d_in[1];
    const float* Wq  = (const float*)d_in[2];
    const float* bq  = (const float*)d_in[3];
    const float* Wk  = (const float*)d_in[4];
    const float* bk  = (const float*)d_in[5];
    const float* Wv  = (const float*)d_in[6];
    const float* bv  = (const float*)d_in[7];
    float* out = (float*)d_out;

    // x + W -> fp16 hi/lo (fused)
    {
        int total = NN * DD / 4 + 3 * DD * DD / 4;
        split_kernel<<<(total + 255) / 256, 256>>>(x, Wq, Wk, Wv);
    }

    // q/k/v projections via mma (k written directly as hi/lo splits)
    cudaFuncSetAttribute(qkvmma_kernel, cudaFuncAttributeMaxDynamicSharedMemorySize,
                         QNSTAGE * QSTAGE_B);
    dim3 gq(NN / 128, 2, 3);
    qkvmma_kernel<<<gq, 256, QNSTAGE * QSTAGE_B>>>(bq, bk, bv);

    // s partials: raw fp32 adj via cp.async + in-pipeline fp16 convert
    // (round-13 pipeline; half-scope named barrier after convert)
    cudaFuncSetAttribute(smma_kernel, cudaFuncAttributeMaxDynamicSharedMemorySize,
                         S_SMEM);
    dim3 gs(NN / 128, 2, 2);
    smma_kernel<<<gs, 256, S_SMEM>>>(adj);

    // softmax (exp + 1/sum only; normalization fused into out_kernel)
    softmax_kernel<<<1, 1024>>>();

    // out = alpha[:,None] * v  (+ normalized alpha tail)
    int write_tail = (out_size >= NN * DD + NN) ? 1 : 0;
    int total = NN * DD / 4 + NN / 4;
    out_kernel<<<(total + 255) / 256, 256>>>(out, write_tail);
}

// round 16
// speedup vs baseline: 1.1631x; 1.0147x over previous
#include <cuda_runtime.h>
#include <cuda_fp16.h>
#include <cstdint>

#define NN 8192
#define DD 256

// ---------------- scratch (device globals; no allocation allowed) ----------
__device__ float  g_q[NN * DD];
__device__ float  g_v[NN * DD];
__device__ __half g_xh[NN * DD];              // x hi split
__device__ __half g_xl[NN * DD];              // x lo split
__device__ __half g_wh[3 * DD * DD];          // Wq|Wk|Wv hi split
__device__ __half g_wl[3 * DD * DD];          // Wq|Wk|Wv lo split
__device__ __half g_kh[NN * DD];              // k hi split [j][d]
__device__ __half g_kl[NN * DD];              // k lo split
__device__ float  g_spart[4 * NN];            // deterministic partials
__device__ float  g_alpha[NN];                // exp(s - max) (unnormalized)
__device__ float  g_inv;                      // 1 / sum(exp)

// ---------------- PTX helpers (base sm_80+ ISA only) ------------------------
__device__ __forceinline__ uint32_t cvta_smem(const void* p) {
    uint32_t a;
    asm("{ .reg .u64 t; cvta.to.shared.u64 t, %1; cvt.u32.u64 %0, t; }"
        : "=r"(a) : "l"(p));
    return a;
}
__device__ __forceinline__ void cp16(uint32_t dst, const void* src) {
    asm volatile("cp.async.cg.shared.global [%0], [%1], 16;" :: "r"(dst), "l"(src));
}
__device__ __forceinline__ void cp_commit() {
    asm volatile("cp.async.commit_group;" ::: "memory");
}
template <int N>
__device__ __forceinline__ void cp_wait() {
    asm volatile("cp.async.wait_group %0;" :: "n"(N) : "memory");
}
__device__ __forceinline__ void ldm_x4(uint32_t addr, uint32_t& r0, uint32_t& r1,
                                       uint32_t& r2, uint32_t& r3) {
    asm volatile("ldmatrix.sync.aligned.m8n8.x4.shared.b16 {%0,%1,%2,%3}, [%4];"
                 : "=r"(r0), "=r"(r1), "=r"(r2), "=r"(r3) : "r"(addr));
}
__device__ __forceinline__ void ldm_x4_t(uint32_t addr, uint32_t& r0, uint32_t& r1,
                                         uint32_t& r2, uint32_t& r3) {
    asm volatile("ldmatrix.sync.aligned.m8n8.x4.trans.shared.b16 {%0,%1,%2,%3}, [%4];"
                 : "=r"(r0), "=r"(r1), "=r"(r2), "=r"(r3) : "r"(addr));
}
__device__ __forceinline__ void mma16816(float* c, const uint32_t* a,
                                         uint32_t b0, uint32_t b1) {
    asm volatile(
        "mma.sync.aligned.m16n8k16.row.col.f32.f16.f16.f32 "
        "{%0,%1,%2,%3}, {%4,%5,%6,%7}, {%8,%9}, {%0,%1,%2,%3};"
        : "+f"(c[0]), "+f"(c[1]), "+f"(c[2]), "+f"(c[3])
        : "r"(a[0]), "r"(a[1]), "r"(a[2]), "r"(a[3]), "r"(b0), "r"(b1));
}

// ---------------------------------------------------------------------------
// fused x-split + W-split
// ---------------------------------------------------------------------------
__global__ __launch_bounds__(256) void split_kernel(const float* __restrict__ x,
                                                    const float* __restrict__ Wq,
                                                    const float* __restrict__ Wk,
                                                    const float* __restrict__ Wv)
{
    const int X4 = NN * DD / 4;
    const int W4 = DD * DD / 4;
    int i4 = blockIdx.x * blockDim.x + threadIdx.x;
    const float* src;
    __half *dh, *dl;
    size_t off;
    if (i4 < X4) {
        src = x; dh = g_xh; dl = g_xl; off = (size_t)i4 * 4;
    } else if (i4 < X4 + 3 * W4) {
        int r = i4 - X4;
        int z = r / W4;
        int w = r - z * W4;
        src = (z == 0) ? Wq : (z == 1) ? Wk : Wv;
        dh = g_wh + (size_t)z * DD * DD;
        dl = g_wl + (size_t)z * DD * DD;
        off = (size_t)w * 4;
    } else {
        return;
    }
    float4 v4 = *(const float4*)(src + off);
    float vs[4] = {v4.x, v4.y, v4.z, v4.w};
    __half hi[4], lo[4];
    #pragma unroll
    for (int i = 0; i < 4; i++) {
        hi[i] = __float2half_rn(vs[i]);
        lo[i] = __float2half_rn(vs[i] - __half2float(hi[i]));
    }
    *(__half2*)(dh + off)     = __halves2half2(hi[0], hi[1]);
    *(__half2*)(dh + off + 2) = __halves2half2(hi[2], hi[3]);
    *(__half2*)(dl + off)     = __halves2half2(lo[0], lo[1]);
    *(__half2*)(dl + off + 2) = __halves2half2(lo[2], lo[3]);
}

// ---------------------------------------------------------------------------
// q/k/v = x @ W + b via mma.sync; KC=32, 2 stages, 2 CTAs/SM.
// grid (64, 2, 3). z==1 (k) epilogue writes g_kh/g_kl directly.
// ---------------------------------------------------------------------------
#define Q_ITERS   (DD / 32)                 // 8
#define QLDA      40
#define QLDB      136
#define QA_B      (128 * QLDA * 2)          // 10240 per split
#define QB_B      (32 * QLDB * 2)           // 8704 per split
#define QSTAGE_B  (2 * QA_B + 2 * QB_B)     // 37888
#define QNSTAGE   2

__global__ __launch_bounds__(256, 2) void qkvmma_kernel(
    const float* __restrict__ bq, const float* __restrict__ bk,
    const float* __restrict__ bv)
{
    extern __shared__ char smem[];
    const int tid  = threadIdx.x;
    const int wid  = tid >> 5;
    const int lane = tid & 31;
    const int warp_m = wid >> 1;
    const int warp_n = wid & 1;
    const int row0 = blockIdx.x * 128;
    const int n0   = blockIdx.y * 128;
    const int z    = blockIdx.z;
    const __half* Wh = g_wh + (size_t)z * DD * DD;
    const __half* Wl = g_wl + (size_t)z * DD * DD;
    const uint32_t sbase = cvta_smem(smem);

    float acc[2][8][4];
    #pragma unroll
    for (int m = 0; m < 2; m++)
        #pragma unroll
        for (int n = 0; n < 8; n++)
            #pragma unroll
            for (int i = 0; i < 4; i++) acc[m][n][i] = 0.0f;

    #define LOAD_STAGE_Q(st, it)                                                \
    do {                                                                         \
        const int j0 = (it) * 32;                                               \
        const uint32_t sah = sbase + (st) * QSTAGE_B;                           \
        const uint32_t sal = sah + QA_B;                                        \
        const uint32_t sbh = sal + QA_B;                                        \
        const uint32_t sbl = sbh + QB_B;                                        \
        _Pragma("unroll")                                                       \
        for (int u = 0; u < 2; u++) {                                           \
            int c = tid + u * 256;              /* 0..511 */                    \
            int r  = c >> 2;                     /* 0..127 */                   \
            int k8 = (c & 3) * 8;                                               \
            uint32_t off = (uint32_t)(r * QLDA + k8) * 2;                       \
            cp16(sah + off, g_xh + (size_t)(row0 + r) * DD + j0 + k8);          \
            cp16(sal + off, g_xl + (size_t)(row0 + r) * DD + j0 + k8);          \
        }                                                                       \
        _Pragma("unroll")                                                       \
        for (int u = 0; u < 2; u++) {                                           \
            int c = tid + u * 256;                                              \
            int r  = c >> 4;                     /* 0..31 */                    \
            int n8 = (c & 15) * 8;                                              \
            uint32_t off = (uint32_t)(r * QLDB + n8) * 2;                       \
            cp16(sbh + off, Wh + (size_t)(j0 + r) * DD + n0 + n8);              \
            cp16(sbl + off, Wl + (size_t)(j0 + r) * DD + n0 + n8);              \
        }                                                                       \
    } while (0)

    LOAD_STAGE_Q(0, 0); cp_commit();
    LOAD_STAGE_Q(1, 1); cp_commit();

    int buf = 0;
    for (int it = 0; it < Q_ITERS; ++it) {
        cp_wait<1>();
        __syncthreads();
        const uint32_t sah = sbase + buf * QSTAGE_B;
        const uint32_t sal = sah + QA_B;
        const uint32_t sbh = sal + QA_B;
        const uint32_t sbl = sbh + QB_B;

        #pragma unroll
        for (int kk = 0; kk < 2; kk++) {
            uint32_t ah[2][4], al[2][4];
            #pragma unroll
            for (int mf = 0; mf < 2; mf++) {
                int arow = warp_m * 32 + mf * 16 + (lane & 15);
                int acol = kk * 16 + (lane >> 4) * 8;
                uint32_t off = (uint32_t)(arow * QLDA + acol) * 2;
                ldm_x4(sah + off, ah[mf][0], ah[mf][1], ah[mf][2], ah[mf][3]);
                ldm_x4(sal + off, al[mf][0], al[mf][1], al[mf][2], al[mf][3]);
            }
            uint32_t b[8][2];
            #pragma unroll
            for (int nq = 0; nq < 4; nq++) {
                int brow = kk * 16 + (lane & 15);
                int bcol = warp_n * 64 + nq * 16 + (lane >> 4) * 8;
                uint32_t off = (uint32_t)(brow * QLDB + bcol) * 2;
                ldm_x4_t(sbh + off, b[nq*2][0], b[nq*2][1], b[nq*2+1][0], b[nq*2+1][1]);
            }
            #pragma unroll
            for (int mf = 0; mf < 2; mf++)
                #pragma unroll
                for (int nf = 0; nf < 8; nf++) {
                    mma16816(acc[mf][nf], ah[mf], b[nf][0], b[nf][1]);
                    mma16816(acc[mf][nf], al[mf], b[nf][0], b[nf][1]);
                }
            #pragma unroll
            for (int nq = 0; nq < 4; nq++) {
                int brow = kk * 16 + (lane & 15);
                int bcol = warp_n * 64 + nq * 16 + (lane >> 4) * 8;
                uint32_t off = (uint32_t)(brow * QLDB + bcol) * 2;
                ldm_x4_t(sbl + off, b[nq*2][0], b[nq*2][1], b[nq*2+1][0], b[nq*2+1][1]);
            }
            #pragma unroll
            for (int mf = 0; mf < 2; mf++)
                #pragma unroll
                for (int nf = 0; nf < 8; nf++)
                    mma16816(acc[mf][nf], ah[mf], b[nf][0], b[nf][1]);
        }
        __syncthreads();
        if (it + QNSTAGE < Q_ITERS) LOAD_STAGE_Q(buf, it + QNSTAGE);
        cp_commit();
        if (++buf == QNSTAGE) buf = 0;
    }

    const float* bias = (z == 0) ? bq : (z == 1) ? bk : bv;
    #pragma unroll
    for (int mf = 0; mf < 2; mf++) {
        #pragma unroll
        for (int rr = 0; rr < 2; rr++) {
            int row = row0 + warp_m * 32 + mf * 16 + rr * 8 + (lane >> 2);
            #pragma unroll
            for (int nf = 0; nf < 8; nf++) {
                int col = n0 + warp_n * 64 + nf * 8 + (lane & 3) * 2;
                float v0 = acc[mf][nf][rr * 2 + 0] + bias[col];
                float v1 = acc[mf][nf][rr * 2 + 1] + bias[col + 1];
                size_t o = (size_t)row * DD + col;
                if (z == 0) {
                    *(float2*)(g_q + o) = make_float2(v0, v1);
                } else if (z == 2) {
                    *(float2*)(g_v + o) = make_float2(v0, v1);
                } else {
                    __half h0 = __float2half_rn(v0);
                    __half h1 = __float2half_rn(v1);
                    __half l0 = __float2half_rn(v0 - __half2float(h0));
                    __half l1 = __float2half_rn(v1 - __half2float(h1));
                    *(__half2*)(g_kh + o) = __halves2half2(h0, h1);
                    *(__half2*)(g_kl + o) = __halves2half2(l0, l1);
                }
            }
        }
    }
}

// ---------------------------------------------------------------------------
// s partials via fp16 mma.sync; raw fp32 adj cp.async'd + in-pipeline convert.
// EXACT round-13 pipeline (measured best 236.2us): cp_wait<1>; sync;
// load(i+2); commit; convert(i); sync; mma(i).
// NEW (only change): ldmatrix smem offsets fully precomputed outside the
// 128-iteration mainloop (pure add inside), shrinking the per-iter ALU stream
// that competes with HMMA issue.
// Grid (64, 2, 2), 256 threads, 2 CTAs/SM, KC=32, 3-stage ring, 2m x 4n warps.
// ---------------------------------------------------------------------------
#define S_ITERS   (NN / 2 / 32)             // 128
#define SLDA      40                         // fp16 A buffer stride (halfs)
#define SLDB      136
#define SA32_B    (128 * 32 * 4)            // 16384 (raw fp32 adj tile)
#define SB_B      (32 * SLDB * 2)           // 8704
#define SSTAGE_B  (SA32_B + 2 * SB_B)       // 33792
#define SNSTAGE   3
#define A16_OFF   (SNSTAGE * SSTAGE_B)      // 101376
#define A16_B     (128 * SLDA * 2)          // 10240
#define S_SMEM    (A16_OFF + A16_B)         // 111616

__global__ __launch_bounds__(256, 2) void smma_kernel(const float* __restrict__ adj)
{
    extern __shared__ char smem[];

    const int tid  = threadIdx.x;
    const int wid  = tid >> 5;
    const int lane = tid & 31;
    const int warp_m = wid >> 2;      // 0..1 (64 rows each)
    const int warp_n = wid & 3;       // 0..3 (32 cols each)
    const int row0 = blockIdx.x * 128;
    const int n0   = blockIdx.y * 128;
    const int kbase = blockIdx.z * (NN / 2);
    const uint32_t sbase = cvta_smem(smem);
    const uint32_t a16   = sbase + A16_OFF;

    // ---- precomputed ldmatrix offsets (loop-invariant) ----
    // A: a16 + (arow*SLDA + acol)*2 for mf=0..3, kk=0..1
    uint32_t a_addr[2][4];
    #pragma unroll
    for (int kk = 0; kk < 2; kk++)
        #pragma unroll
        for (int mf = 0; mf < 4; mf++) {
            int arow = warp_m * 64 + mf * 16 + (lane & 15);
            int acol = kk * 16 + (lane >> 4) * 8;
            a_addr[kk][mf] = a16 + (uint32_t)(arow * SLDA + acol) * 2;
        }
    // B: (brow*SLDB + bcol)*2 for ng=0..1, kk=0..1 (relative to sh/sl base)
    uint32_t b_off[2][2];
    #pragma unroll
    for (int kk = 0; kk < 2; kk++)
        #pragma unroll
        for (int ng = 0; ng < 2; ng++) {
            int brow = kk * 16 + (lane & 15);
            int bcol = warp_n * 32 + ng * 16 + (lane >> 4) * 8;
            b_off[kk][ng] = (uint32_t)(brow * SLDB + bcol) * 2;
        }

    float acc[4][4][4];
    #pragma unroll
    for (int m = 0; m < 4; m++)
        #pragma unroll
        for (int n = 0; n < 4; n++)
            #pragma unroll
            for (int i = 0; i < 4; i++) acc[m][n][i] = 0.0f;

    #define LOAD_STAGE_S(st, it)                                                \
    do {                                                                         \
        const int j0 = kbase + (it) * 32;                                       \
        const uint32_t sa32 = sbase + (st) * SSTAGE_B;                          \
        const uint32_t shh = sa32 + SA32_B;                                     \
        const uint32_t sll = shh + SB_B;                                        \
        _Pragma("unroll")                                                       \
        for (int u = 0; u < 4; u++) {                                           \
            int c = tid + u * 256;              /* 0..1023 */                   \
            int r  = c >> 3;                     /* 0..127 */                   \
            int k4 = (c & 7) * 4;                                               \
            cp16(sa32 + (uint32_t)(r * 32 + k4) * 4,                            \
                 adj + (size_t)(row0 + r) * NN + j0 + k4);                      \
        }                                                                       \
        _Pragma("unroll")                                                       \
        for (int u = 0; u < 2; u++) {                                           \
            int c = tid + u * 256;                                              \
            int r  = c >> 4;                     /* 0..31 */                    \
            int n8 = (c & 15) * 8;                                              \
            uint32_t off = (uint32_t)(r * SLDB + n8) * 2;                       \
            cp16(shh + off, g_kh + (size_t)(j0 + r) * DD + n0 + n8);            \
            cp16(sll + off, g_kl + (size_t)(j0 + r) * DD + n0 + n8);            \
        }                                                                       \
    } while (0)

    LOAD_STAGE_S(0, 0); cp_commit();
    LOAD_STAGE_S(1, 1); cp_commit();

    int buf = 0;       // it % 3
    int nxt = 2;       // (it+2) % 3
    for (int it = 0; it < S_ITERS; ++it) {
        cp_wait<1>();
        __syncthreads();        // stage `buf` data ready; stage `nxt` buffer free

        // prefetch stage it+2 into the buffer consumed at it-1
        if (it + 2 < S_ITERS) LOAD_STAGE_S(nxt, it + 2);
        cp_commit();

        const uint32_t sa32 = sbase + buf * SSTAGE_B;
        const uint32_t sh = sa32 + SA32_B;
        const uint32_t sl = sh + SB_B;

        // convert fp32 adj tile -> fp16 A buffer (smem->smem, all threads)
        {
            const char* a32p = smem + (size_t)buf * SSTAGE_B;
            #pragma unroll
            for (int u = 0; u < 4; u++) {
                int c = tid + u * 256;
                int r  = c >> 3;
                int k4 = (c & 7) * 4;
                float4 v = *(const float4*)(a32p + (size_t)(r * 32 + k4) * 4);
                __half2 h01 = __floats2half2_rn(v.x, v.y);
                __half2 h23 = __floats2half2_rn(v.z, v.w);
                char* dst = smem + A16_OFF + (size_t)(r * SLDA + k4) * 2;
                *(__half2*)(dst)     = h01;
                *(__half2*)(dst + 4) = h23;
            }
        }
        __syncthreads();        // A16 visible to all warps

        #pragma unroll
        for (int kk = 0; kk < 2; kk++) {
            uint32_t a[4][4];
            #pragma unroll
            for (int mf = 0; mf < 4; mf++)
                ldm_x4(a_addr[kk][mf],
                       a[mf][0], a[mf][1], a[mf][2], a[mf][3]);
            uint32_t b[4][2];
            #pragma unroll
            for (int ng = 0; ng < 2; ng++)
                ldm_x4_t(sh + b_off[kk][ng],
                         b[ng*2][0], b[ng*2][1], b[ng*2+1][0], b[ng*2+1][1]);
            #pragma unroll
            for (int mf = 0; mf < 4; mf++)
                #pragma unroll
                for (int nf = 0; nf < 4; nf++)
                    mma16816(acc[mf][nf], a[mf], b[nf][0], b[nf][1]);
            #pragma unroll
            for (int ng = 0; ng < 2; ng++)
                ldm_x4_t(sl + b_off[kk][ng],
                         b[ng*2][0], b[ng*2][1], b[ng*2+1][0], b[ng*2+1][1]);
            #pragma unroll
            for (int mf = 0; mf < 4; mf++)
                #pragma unroll
                for (int nf = 0; nf < 4; nf++)
                    mma16816(acc[mf][nf], a[mf], b[nf][0], b[nf][1]);
        }

        buf = (buf == 2) ? 0 : buf + 1;
        nxt = (nxt == 2) ? 0 : nxt + 1;
    }

    // fused epilogue: p[row] = sum_n m[row][n] * q[row][n0+n]
    // srow scratch reuses the A16 buffer region (free after mainloop).
    __syncthreads();
    float* srow = (float*)(smem + A16_OFF);
    #pragma unroll
    for (int mf = 0; mf < 4; mf++) {
        #pragma unroll
        for (int rr = 0; rr < 2; rr++) {
            int lrow = warp_m * 64 + mf * 16 + rr * 8 + (lane >> 2);
            int grow = row0 + lrow;
            float p = 0.0f;
            #pragma unroll
            for (int nf = 0; nf < 4; nf++) {
                int gcol = n0 + warp_n * 32 + nf * 8 + (lane & 3) * 2;
                float2 qq = *(const float2*)(g_q + (size_t)grow * DD + gcol);
                p += acc[mf][nf][rr * 2 + 0] * qq.x
                   + acc[mf][nf][rr * 2 + 1] * qq.y;
            }
            p += __shfl_xor_sync(0xffffffffu, p, 1);
            p += __shfl_xor_sync(0xffffffffu, p, 2);
            if ((lane & 3) == 0) srow[warp_n * 128 + lrow] = p;
        }
    }
    __syncthreads();
    if (tid < 128)
        g_spart[(size_t)(blockIdx.y * 2 + blockIdx.z) * NN + row0 + tid] =
            srow[0 * 128 + tid] + srow[1 * 128 + tid] +
            srow[2 * 128 + tid] + srow[3 * 128 + tid];
}

// ---------------------------------------------------------------------------
// softmax: combine 4 partials, max, exp, sum; store exp() in g_alpha,
// 1/sum in g_inv. Normalization folded into out_kernel.
// ---------------------------------------------------------------------------
__global__ __launch_bounds__(1024) void softmax_kernel()
{
    __shared__ float red[32];
    const int tid = threadIdx.x;
    const int lane = tid & 31;
    const int wid = tid >> 5;

    float sv[8];
    float lmax = -3.4e38f;
    #pragma unroll
    for (int u = 0; u < 8; u++) {
        int i = tid + u * 1024;
        float s = g_spart[i] + g_spart[NN + i] + g_spart[2 * NN + i] + g_spart[3 * NN + i];
        sv[u] = s;
        lmax = fmaxf(lmax, s);
    }
    #pragma unroll
    for (int off = 16; off > 0; off >>= 1)
        lmax = fmaxf(lmax, __shfl_xor_sync(0xffffffffu, lmax, off));
    if (lane == 0) red[wid] = lmax;
    __syncthreads();
    float m = red[lane];
    #pragma unroll
    for (int off = 16; off > 0; off >>= 1)
        m = fmaxf(m, __shfl_xor_sync(0xffffffffu, m, off));
    __syncthreads();

    float lsum = 0.0f;
    #pragma unroll
    for (int u = 0; u < 8; u++) {
        int i = tid + u * 1024;
        float e = expf(sv[u] - m);
        g_alpha[i] = e;
        lsum += e;
    }
    #pragma unroll
    for (int off = 16; off > 0; off >>= 1)
        lsum += __shfl_xor_sync(0xffffffffu, lsum, off);
    if (lane == 0) red[wid] = lsum;
    __syncthreads();
    float ssum = red[lane];
    #pragma unroll
    for (int off = 16; off > 0; off >>= 1)
        ssum += __shfl_xor_sync(0xffffffffu, ssum, off);
    if (tid == 0) g_inv = 1.0f / ssum;
}

// ---------------------------------------------------------------------------
// out[i, :] = (alpha_exp[i] * inv) * v[i, :]; + normalized alpha tail.
// ---------------------------------------------------------------------------
__global__ __launch_bounds__(256) void out_kernel(float* __restrict__ out,
                                                  int write_tail)
{
    const int total4 = NN * DD / 4;
    int idx = blockIdx.x * blockDim.x + threadIdx.x;
    float inv = g_inv;
    if (idx < total4) {
        int row = (idx * 4) / DD;
        float a = g_alpha[row] * inv;
        float4 v4 = *(const float4*)(g_v + (size_t)idx * 4);
        v4.x *= a; v4.y *= a; v4.z *= a; v4.w *= a;
        *(float4*)(out + (size_t)idx * 4) = v4;
    } else if (idx < total4 + NN / 4) {
        if (write_tail) {
            int j = (idx - total4) * 4;
            float4 a4 = *(const float4*)(g_alpha + j);
            a4.x *= inv; a4.y *= inv; a4.z *= inv; a4.w *= inv;
            *(float4*)(out + (size_t)NN * DD + j) = a4;
        }
    }
}

// ---------------------------------------------------------------------------
extern "C" void kernel_launch(void* const* d_in, const int* in_sizes, int n_in,
                              void* d_out, int out_size) {
    const float* x   = (const float*)d_in[0];
    const float* adj = (const float*)d_in[1];
    const float* Wq  = (const float*)d_in[2];
    const float* bq  = (const float*)d_in[3];
    const float* Wk  = (const float*)d_in[4];
    const float* bk  = (const float*)d_in[5];
    const float* Wv  = (const float*)d_in[6];
    const float* bv  = (const float*)d_in[7];
    float* out = (float*)d_out;

    // x + W -> fp16 hi/lo (fused)
    {
        int total = NN * DD / 4 + 3 * DD * DD / 4;
        split_kernel<<<(total + 255) / 256, 256>>>(x, Wq, Wk, Wv);
    }

    // q/k/v projections via mma (k written directly as hi/lo splits)
    cudaFuncSetAttribute(qkvmma_kernel, cudaFuncAttributeMaxDynamicSharedMemorySize,
                         QNSTAGE * QSTAGE_B);
    dim3 gq(NN / 128, 2, 3);
    qkvmma_kernel<<<gq, 256, QNSTAGE * QSTAGE_B>>>(bq, bk, bv);

    // s partials: raw fp32 adj via cp.async + in-pipeline fp16 convert
    // (round-13 pipeline; hoisted ldmatrix addressing)
    cudaFuncSetAttribute(smma_kernel, cudaFuncAttributeMaxDynamicSharedMemorySize,
                         S_SMEM);
    dim3 gs(NN / 128, 2, 2);
    smma_kernel<<<gs, 256, S_SMEM>>>(adj);

    // softmax (exp + 1/sum only; normalization fused into out_kernel)
    softmax_kernel<<<1, 1024>>>();

    // out = alpha[:,None] * v  (+ normalized alpha tail)
    int write_tail = (out_size >= NN * DD + NN) ? 1 : 0;
    int total = NN * DD / 4 + NN / 4;
    out_kernel<<<(total + 255) / 256, 256>>>(out, write_tail);
}

// round 17
// speedup vs baseline: 1.1674x; 1.0037x over previous
#include <cuda_runtime.h>
#include <cuda_fp16.h>
#include <cstdint>

#define NN 8192
#define DD 256

// ---------------- scratch (device globals; no allocation allowed) ----------
__device__ float  g_q[NN * DD];
__device__ float  g_v[NN * DD];
__device__ __half g_kh[NN * DD];              // k hi split [j][d]
__device__ __half g_kl[NN * DD];              // k lo split
__device__ float  g_spart[4 * NN];            // deterministic partials
__device__ float  g_alpha[NN];                // exp(s - max) (unnormalized)
__device__ float  g_inv;                      // 1 / sum(exp)

// ---------------- PTX helpers (base sm_80+ ISA only) ------------------------
__device__ __forceinline__ uint32_t cvta_smem(const void* p) {
    uint32_t a;
    asm("{ .reg .u64 t; cvta.to.shared.u64 t, %1; cvt.u32.u64 %0, t; }"
        : "=r"(a) : "l"(p));
    return a;
}
__device__ __forceinline__ void cp16(uint32_t dst, const void* src) {
    asm volatile("cp.async.cg.shared.global [%0], [%1], 16;" :: "r"(dst), "l"(src));
}
__device__ __forceinline__ void cp_commit() {
    asm volatile("cp.async.commit_group;" ::: "memory");
}
template <int N>
__device__ __forceinline__ void cp_wait() {
    asm volatile("cp.async.wait_group %0;" :: "n"(N) : "memory");
}
__device__ __forceinline__ void ldm_x4(uint32_t addr, uint32_t& r0, uint32_t& r1,
                                       uint32_t& r2, uint32_t& r3) {
    asm volatile("ldmatrix.sync.aligned.m8n8.x4.shared.b16 {%0,%1,%2,%3}, [%4];"
                 : "=r"(r0), "=r"(r1), "=r"(r2), "=r"(r3) : "r"(addr));
}
__device__ __forceinline__ void ldm_x4_t(uint32_t addr, uint32_t& r0, uint32_t& r1,
                                         uint32_t& r2, uint32_t& r3) {
    asm volatile("ldmatrix.sync.aligned.m8n8.x4.trans.shared.b16 {%0,%1,%2,%3}, [%4];"
                 : "=r"(r0), "=r"(r1), "=r"(r2), "=r"(r3) : "r"(addr));
}
__device__ __forceinline__ void mma16816(float* c, const uint32_t* a,
                                         uint32_t b0, uint32_t b1) {
    asm volatile(
        "mma.sync.aligned.m16n8k16.row.col.f32.f16.f16.f32 "
        "{%0,%1,%2,%3}, {%4,%5,%6,%7}, {%8,%9}, {%0,%1,%2,%3};"
        : "+f"(c[0]), "+f"(c[1]), "+f"(c[2]), "+f"(c[3])
        : "r"(a[0]), "r"(a[1]), "r"(a[2]), "r"(a[3]), "r"(b0), "r"(b1));
}

// ---------------------------------------------------------------------------
// q/k/v = x @ W + b via mma.sync, fp32 inputs staged via cp.async and
// hi/lo-split IN-KERNEL (split_kernel eliminated). KC=32, 2 raw stages,
// single convert buffer set, 2 CTAs/SM. grid (64, 2, 3).
// z==1 (k) epilogue writes g_kh/g_kl directly.
// ---------------------------------------------------------------------------
#define Q_ITERS   (DD / 32)                 // 8
#define QLDA      40
#define QLDB      136
#define QX32_B    (128 * 32 * 4)            // 16384 raw x tile
#define QW32_B    (32 * 128 * 4)            // 16384 raw W tile
#define QSTG_B    (QX32_B + QW32_B)         // 32768 per stage
#define QCONV_OFF (2 * QSTG_B)              // 65536
#define QXH_B     (128 * QLDA * 2)          // 10240
#define QWH_B     (32 * QLDB * 2)           // 8704
#define Q_SMEM    (QCONV_OFF + 2 * QXH_B + 2 * QWH_B)   // 103424

__global__ __launch_bounds__(256, 2) void qkvmma_kernel(
    const float* __restrict__ x,
    const float* __restrict__ Wq, const float* __restrict__ Wk,
    const float* __restrict__ Wv,
    const float* __restrict__ bq, const float* __restrict__ bk,
    const float* __restrict__ bv)
{
    extern __shared__ char smem[];
    const int tid  = threadIdx.x;
    const int wid  = tid >> 5;
    const int lane = tid & 31;
    const int warp_m = wid >> 1;
    const int warp_n = wid & 1;
    const int row0 = blockIdx.x * 128;
    const int n0   = blockIdx.y * 128;
    const int z    = blockIdx.z;
    const float* W = (z == 0) ? Wq : (z == 1) ? Wk : Wv;
    const uint32_t sbase = cvta_smem(smem);
    const uint32_t xh = sbase + QCONV_OFF;
    const uint32_t xl = xh + QXH_B;
    const uint32_t wh = xl + QXH_B;
    const uint32_t wl = wh + QWH_B;

    // hoisted ldmatrix addresses (loop-invariant)
    uint32_t xa_off[2][2];       // [kk][mf]  offset into xh/xl
    #pragma unroll
    for (int kk = 0; kk < 2; kk++)
        #pragma unroll
        for (int mf = 0; mf < 2; mf++) {
            int arow = warp_m * 32 + mf * 16 + (lane & 15);
            int acol = kk * 16 + (lane >> 4) * 8;
            xa_off[kk][mf] = (uint32_t)(arow * QLDA + acol) * 2;
        }
    uint32_t wb_off[2][4];       // [kk][nq]  offset into wh/wl
    #pragma unroll
    for (int kk = 0; kk < 2; kk++)
        #pragma unroll
        for (int nq = 0; nq < 4; nq++) {
            int brow = kk * 16 + (lane & 15);
            int bcol = warp_n * 64 + nq * 16 + (lane >> 4) * 8;
            wb_off[kk][nq] = (uint32_t)(brow * QLDB + bcol) * 2;
        }

    float acc[2][8][4];
    #pragma unroll
    for (int m = 0; m < 2; m++)
        #pragma unroll
        for (int n = 0; n < 8; n++)
            #pragma unroll
            for (int i = 0; i < 4; i++) acc[m][n][i] = 0.0f;

    // load raw fp32 stage `st` with K-chunk `it`
    #define LOAD_STAGE_Q(st, it)                                                \
    do {                                                                         \
        const int j0 = (it) * 32;                                               \
        const uint32_t sx = sbase + (st) * QSTG_B;                              \
        const uint32_t sw = sx + QX32_B;                                        \
        _Pragma("unroll")                                                       \
        for (int u = 0; u < 4; u++) {                                           \
            int c = tid + u * 256;              /* 0..1023 */                   \
            int r  = c >> 3;                     /* 0..127 */                   \
            int k4 = (c & 7) * 4;                                               \
            cp16(sx + (uint32_t)(r * 32 + k4) * 4,                              \
                 x + (size_t)(row0 + r) * DD + j0 + k4);                        \
        }                                                                       \
        _Pragma("unroll")                                                       \
        for (int u = 0; u < 4; u++) {                                           \
            int c = tid + u * 256;                                              \
            int r  = c >> 5;                     /* 0..31 */                    \
            int n4 = (c & 31) * 4;                                              \
            cp16(sw + (uint32_t)(r * 128 + n4) * 4,                             \
                 W + (size_t)(j0 + r) * DD + n0 + n4);                          \
        }                                                                       \
    } while (0)

    LOAD_STAGE_Q(0, 0); cp_commit();
    LOAD_STAGE_Q(1, 1); cp_commit();

    int buf = 0;
    for (int it = 0; it < Q_ITERS; ++it) {
        cp_wait<1>();
        __syncthreads();

        // convert raw fp32 stage -> hi/lo fp16 buffers
        {
            const char* sx = smem + (size_t)buf * QSTG_B;
            const char* sw = sx + QX32_B;
            #pragma unroll
            for (int u = 0; u < 4; u++) {
                int c = tid + u * 256;
                int r  = c >> 3;
                int k4 = (c & 7) * 4;
                float4 v = *(const float4*)(sx + (size_t)(r * 32 + k4) * 4);
                float vs[4] = {v.x, v.y, v.z, v.w};
                __half hi[4], lo[4];
                #pragma unroll
                for (int i = 0; i < 4; i++) {
                    hi[i] = __float2half_rn(vs[i]);
                    lo[i] = __float2half_rn(vs[i] - __half2float(hi[i]));
                }
                size_t d = (size_t)(r * QLDA + k4) * 2;
                *(__half2*)(smem + QCONV_OFF + d)     = __halves2half2(hi[0], hi[1]);
                *(__half2*)(smem + QCONV_OFF + d + 4) = __halves2half2(hi[2], hi[3]);
                *(__half2*)(smem + QCONV_OFF + QXH_B + d)     = __halves2half2(lo[0], lo[1]);
                *(__half2*)(smem + QCONV_OFF + QXH_B + d + 4) = __halves2half2(lo[2], lo[3]);
            }
            #pragma unroll
            for (int u = 0; u < 4; u++) {
                int c = tid + u * 256;
                int r  = c >> 5;
                int n4 = (c & 31) * 4;
                float4 v = *(const float4*)(sw + (size_t)(r * 128 + n4) * 4);
                float vs[4] = {v.x, v.y, v.z, v.w};
                __half hi[4], lo[4];
                #pragma unroll
                for (int i = 0; i < 4; i++) {
                    hi[i] = __float2half_rn(vs[i]);
                    lo[i] = __float2half_rn(vs[i] - __half2float(hi[i]));
                }
                size_t d = (size_t)(r * QLDB + n4) * 2;
                *(__half2*)(smem + QCONV_OFF + 2 * QXH_B + d)     = __halves2half2(hi[0], hi[1]);
                *(__half2*)(smem + QCONV_OFF + 2 * QXH_B + d + 4) = __halves2half2(hi[2], hi[3]);
                *(__half2*)(smem + QCONV_OFF + 2 * QXH_B + QWH_B + d)     = __halves2half2(lo[0], lo[1]);
                *(__half2*)(smem + QCONV_OFF + 2 * QXH_B + QWH_B + d + 4) = __halves2half2(lo[2], lo[3]);
            }
        }
        __syncthreads();

        #pragma unroll
        for (int kk = 0; kk < 2; kk++) {
            uint32_t ah[2][4], al[2][4];
            #pragma unroll
            for (int mf = 0; mf < 2; mf++) {
                ldm_x4(xh + xa_off[kk][mf], ah[mf][0], ah[mf][1], ah[mf][2], ah[mf][3]);
                ldm_x4(xl + xa_off[kk][mf], al[mf][0], al[mf][1], al[mf][2], al[mf][3]);
            }
            uint32_t b[8][2];
            #pragma unroll
            for (int nq = 0; nq < 4; nq++)
                ldm_x4_t(wh + wb_off[kk][nq],
                         b[nq*2][0], b[nq*2][1], b[nq*2+1][0], b[nq*2+1][1]);
            #pragma unroll
            for (int mf = 0; mf < 2; mf++)
                #pragma unroll
                for (int nf = 0; nf < 8; nf++) {
                    mma16816(acc[mf][nf], ah[mf], b[nf][0], b[nf][1]);
                    mma16816(acc[mf][nf], al[mf], b[nf][0], b[nf][1]);
                }
            #pragma unroll
            for (int nq = 0; nq < 4; nq++)
                ldm_x4_t(wl + wb_off[kk][nq],
                         b[nq*2][0], b[nq*2][1], b[nq*2+1][0], b[nq*2+1][1]);
            #pragma unroll
            for (int mf = 0; mf < 2; mf++)
                #pragma unroll
                for (int nf = 0; nf < 8; nf++)
                    mma16816(acc[mf][nf], ah[mf], b[nf][0], b[nf][1]);
        }
        __syncthreads();    // conv-buffer reads done; stage `buf` free
        if (it + 2 < Q_ITERS) LOAD_STAGE_Q(buf, it + 2);
        cp_commit();
        buf ^= 1;
    }

    const float* bias = (z == 0) ? bq : (z == 1) ? bk : bv;
    #pragma unroll
    for (int mf = 0; mf < 2; mf++) {
        #pragma unroll
        for (int rr = 0; rr < 2; rr++) {
            int row = row0 + warp_m * 32 + mf * 16 + rr * 8 + (lane >> 2);
            #pragma unroll
            for (int nf = 0; nf < 8; nf++) {
                int col = n0 + warp_n * 64 + nf * 8 + (lane & 3) * 2;
                float v0 = acc[mf][nf][rr * 2 + 0] + bias[col];
                float v1 = acc[mf][nf][rr * 2 + 1] + bias[col + 1];
                size_t o = (size_t)row * DD + col;
                if (z == 0) {
                    *(float2*)(g_q + o) = make_float2(v0, v1);
                } else if (z == 2) {
                    *(float2*)(g_v + o) = make_float2(v0, v1);
                } else {
                    __half h0 = __float2half_rn(v0);
                    __half h1 = __float2half_rn(v1);
                    __half l0 = __float2half_rn(v0 - __half2float(h0));
                    __half l1 = __float2half_rn(v1 - __half2float(h1));
                    *(__half2*)(g_kh + o) = __halves2half2(h0, h1);
                    *(__half2*)(g_kl + o) = __halves2half2(l0, l1);
                }
            }
        }
    }
}

// ---------------------------------------------------------------------------
// s partials via fp16 mma.sync; raw fp32 adj cp.async'd + in-pipeline convert.
// EXACT round-16 configuration (measured best 234.6us).
// Grid (64, 2, 2), 256 threads, 2 CTAs/SM, KC=32, 3-stage ring, 2m x 4n warps.
// ---------------------------------------------------------------------------
#define S_ITERS   (NN / 2 / 32)             // 128
#define SLDA      40                         // fp16 A buffer stride (halfs)
#define SLDB      136
#define SA32_B    (128 * 32 * 4)            // 16384 (raw fp32 adj tile)
#define SB_B      (32 * SLDB * 2)           // 8704
#define SSTAGE_B  (SA32_B + 2 * SB_B)       // 33792
#define SNSTAGE   3
#define A16_OFF   (SNSTAGE * SSTAGE_B)      // 101376
#define A16_B     (128 * SLDA * 2)          // 10240
#define S_SMEM    (A16_OFF + A16_B)         // 111616

__global__ __launch_bounds__(256, 2) void smma_kernel(const float* __restrict__ adj)
{
    extern __shared__ char smem[];

    const int tid  = threadIdx.x;
    const int wid  = tid >> 5;
    const int lane = tid & 31;
    const int warp_m = wid >> 2;      // 0..1 (64 rows each)
    const int warp_n = wid & 3;       // 0..3 (32 cols each)
    const int row0 = blockIdx.x * 128;
    const int n0   = blockIdx.y * 128;
    const int kbase = blockIdx.z * (NN / 2);
    const uint32_t sbase = cvta_smem(smem);
    const uint32_t a16   = sbase + A16_OFF;

    uint32_t a_addr[2][4];
    #pragma unroll
    for (int kk = 0; kk < 2; kk++)
        #pragma unroll
        for (int mf = 0; mf < 4; mf++) {
            int arow = warp_m * 64 + mf * 16 + (lane & 15);
            int acol = kk * 16 + (lane >> 4) * 8;
            a_addr[kk][mf] = a16 + (uint32_t)(arow * SLDA + acol) * 2;
        }
    uint32_t b_off[2][2];
    #pragma unroll
    for (int kk = 0; kk < 2; kk++)
        #pragma unroll
        for (int ng = 0; ng < 2; ng++) {
            int brow = kk * 16 + (lane & 15);
            int bcol = warp_n * 32 + ng * 16 + (lane >> 4) * 8;
            b_off[kk][ng] = (uint32_t)(brow * SLDB + bcol) * 2;
        }

    float acc[4][4][4];
    #pragma unroll
    for (int m = 0; m < 4; m++)
        #pragma unroll
        for (int n = 0; n < 4; n++)
            #pragma unroll
            for (int i = 0; i < 4; i++) acc[m][n][i] = 0.0f;

    #define LOAD_STAGE_S(st, it)                                                \
    do {                                                                         \
        const int j0 = kbase + (it) * 32;                                       \
        const uint32_t sa32 = sbase + (st) * SSTAGE_B;                          \
        const uint32_t shh = sa32 + SA32_B;                                     \
        const uint32_t sll = shh + SB_B;                                        \
        _Pragma("unroll")                                                       \
        for (int u = 0; u < 4; u++) {                                           \
            int c = tid + u * 256;              /* 0..1023 */                   \
            int r  = c >> 3;                     /* 0..127 */                   \
            int k4 = (c & 7) * 4;                                               \
            cp16(sa32 + (uint32_t)(r * 32 + k4) * 4,                            \
                 adj + (size_t)(row0 + r) * NN + j0 + k4);                      \
        }                                                                       \
        _Pragma("unroll")                                                       \
        for (int u = 0; u < 2; u++) {                                           \
            int c = tid + u * 256;                                              \
            int r  = c >> 4;                     /* 0..31 */                    \
            int n8 = (c & 15) * 8;                                              \
            uint32_t off = (uint32_t)(r * SLDB + n8) * 2;                       \
            cp16(shh + off, g_kh + (size_t)(j0 + r) * DD + n0 + n8);            \
            cp16(sll + off, g_kl + (size_t)(j0 + r) * DD + n0 + n8);            \
        }                                                                       \
    } while (0)

    LOAD_STAGE_S(0, 0); cp_commit();
    LOAD_STAGE_S(1, 1); cp_commit();

    int buf = 0;       // it % 3
    int nxt = 2;       // (it+2) % 3
    for (int it = 0; it < S_ITERS; ++it) {
        cp_wait<1>();
        __syncthreads();

        if (it + 2 < S_ITERS) LOAD_STAGE_S(nxt, it + 2);
        cp_commit();

        const uint32_t sa32 = sbase + buf * SSTAGE_B;
        const uint32_t sh = sa32 + SA32_B;
        const uint32_t sl = sh + SB_B;

        {
            const char* a32p = smem + (size_t)buf * SSTAGE_B;
            #pragma unroll
            for (int u = 0; u < 4; u++) {
                int c = tid + u * 256;
                int r  = c >> 3;
                int k4 = (c & 7) * 4;
                float4 v = *(const float4*)(a32p + (size_t)(r * 32 + k4) * 4);
                __half2 h01 = __floats2half2_rn(v.x, v.y);
                __half2 h23 = __floats2half2_rn(v.z, v.w);
                char* dst = smem + A16_OFF + (size_t)(r * SLDA + k4) * 2;
                *(__half2*)(dst)     = h01;
                *(__half2*)(dst + 4) = h23;
            }
        }
        __syncthreads();

        #pragma unroll
        for (int kk = 0; kk < 2; kk++) {
            uint32_t a[4][4];
            #pragma unroll
            for (int mf = 0; mf < 4; mf++)
                ldm_x4(a_addr[kk][mf],
                       a[mf][0], a[mf][1], a[mf][2], a[mf][3]);
            uint32_t b[4][2];
            #pragma unroll
            for (int ng = 0; ng < 2; ng++)
                ldm_x4_t(sh + b_off[kk][ng],
                         b[ng*2][0], b[ng*2][1], b[ng*2+1][0], b[ng*2+1][1]);
            #pragma unroll
            for (int mf = 0; mf < 4; mf++)
                #pragma unroll
                for (int nf = 0; nf < 4; nf++)
                    mma16816(acc[mf][nf], a[mf], b[nf][0], b[nf][1]);
            #pragma unroll
            for (int ng = 0; ng < 2; ng++)
                ldm_x4_t(sl + b_off[kk][ng],
                         b[ng*2][0], b[ng*2][1], b[ng*2+1][0], b[ng*2+1][1]);
            #pragma unroll
            for (int mf = 0; mf < 4; mf++)
                #pragma unroll
                for (int nf = 0; nf < 4; nf++)
                    mma16816(acc[mf][nf], a[mf], b[nf][0], b[nf][1]);
        }

        buf = (buf == 2) ? 0 : buf + 1;
        nxt = (nxt == 2) ? 0 : nxt + 1;
    }

    // fused epilogue: p[row] = sum_n m[row][n] * q[row][n0+n]
    __syncthreads();
    float* srow = (float*)(smem + A16_OFF);
    #pragma unroll
    for (int mf = 0; mf < 4; mf++) {
        #pragma unroll
        for (int rr = 0; rr < 2; rr++) {
            int lrow = warp_m * 64 + mf * 16 + rr * 8 + (lane >> 2);
            int grow = row0 + lrow;
            float p = 0.0f;
            #pragma unroll
            for (int nf = 0; nf < 4; nf++) {
                int gcol = n0 + warp_n * 32 + nf * 8 + (lane & 3) * 2;
                float2 qq = *(const float2*)(g_q + (size_t)grow * DD + gcol);
                p += acc[mf][nf][rr * 2 + 0] * qq.x
                   + acc[mf][nf][rr * 2 + 1] * qq.y;
            }
            p += __shfl_xor_sync(0xffffffffu, p, 1);
            p += __shfl_xor_sync(0xffffffffu, p, 2);
            if ((lane & 3) == 0) srow[warp_n * 128 + lrow] = p;
        }
    }
    __syncthreads();
    if (tid < 128)
        g_spart[(size_t)(blockIdx.y * 2 + blockIdx.z) * NN + row0 + tid] =
            srow[0 * 128 + tid] + srow[1 * 128 + tid] +
            srow[2 * 128 + tid] + srow[3 * 128 + tid];
}

// ---------------------------------------------------------------------------
// softmax: combine 4 partials, max, exp, sum; store exp() in g_alpha,
// 1/sum in g_inv. Normalization folded into out_kernel.
// ---------------------------------------------------------------------------
__global__ __launch_bounds__(1024) void softmax_kernel()
{
    __shared__ float red[32];
    const int tid = threadIdx.x;
    const int lane = tid & 31;
    const int wid = tid >> 5;

    float sv[8];
    float lmax = -3.4e38f;
    #pragma unroll
    for (int u = 0; u < 8; u++) {
        int i = tid + u * 1024;
        float s = g_spart[i] + g_spart[NN + i] + g_spart[2 * NN + i] + g_spart[3 * NN + i];
        sv[u] = s;
        lmax = fmaxf(lmax, s);
    }
    #pragma unroll
    for (int off = 16; off > 0; off >>= 1)
        lmax = fmaxf(lmax, __shfl_xor_sync(0xffffffffu, lmax, off));
    if (lane == 0) red[wid] = lmax;
    __syncthreads();
    float m = red[lane];
    #pragma unroll
    for (int off = 16; off > 0; off >>= 1)
        m = fmaxf(m, __shfl_xor_sync(0xffffffffu, m, off));
    __syncthreads();

    float lsum = 0.0f;
    #pragma unroll
    for (int u = 0; u < 8; u++) {
        int i = tid + u * 1024;
        float e = expf(sv[u] - m);
        g_alpha[i] = e;
        lsum += e;
    }
    #pragma unroll
    for (int off = 16; off > 0; off >>= 1)
        lsum += __shfl_xor_sync(0xffffffffu, lsum, off);
    if (lane == 0) red[wid] = lsum;
    __syncthreads();
    float ssum = red[lane];
    #pragma unroll
    for (int off = 16; off > 0; off >>= 1)
        ssum += __shfl_xor_sync(0xffffffffu, ssum, off);
    if (tid == 0) g_inv = 1.0f / ssum;
}

// ---------------------------------------------------------------------------
// out[i, :] = (alpha_exp[i] * inv) * v[i, :]; + normalized alpha tail.
// ---------------------------------------------------------------------------
__global__ __launch_bounds__(256) void out_kernel(float* __restrict__ out,
                                                  int write_tail)
{
    const int total4 = NN * DD / 4;
    int idx = blockIdx.x * blockDim.x + threadIdx.x;
    float inv = g_inv;
    if (idx < total4) {
        int row = (idx * 4) / DD;
        float a = g_alpha[row] * inv;
        float4 v4 = *(const float4*)(g_v + (size_t)idx * 4);
        v4.x *= a; v4.y *= a; v4.z *= a; v4.w *= a;
        *(float4*)(out + (size_t)idx * 4) = v4;
    } else if (idx < total4 + NN / 4) {
        if (write_tail) {
            int j = (idx - total4) * 4;
            float4 a4 = *(const float4*)(g_alpha + j);
            a4.x *= inv; a4.y *= inv; a4.z *= inv; a4.w *= inv;
            *(float4*)(out + (size_t)NN * DD + j) = a4;
        }
    }
}

// ---------------------------------------------------------------------------
extern "C" void kernel_launch(void* const* d_in, const int* in_sizes, int n_in,
                              void* d_out, int out_size) {
    const float* x   = (const float*)d_in[0];
    const float* adj = (const float*)d_in[1];
    const float* Wq  = (const float*)d_in[2];
    const float* bq  = (const float*)d_in[3];
    const float* Wk  = (const float*)d_in[4];
    const float* bk  = (const float*)d_in[5];
    const float* Wv  = (const float*)d_in[6];
    const float* bv  = (const float*)d_in[7];
    float* out = (float*)d_out;

    // q/k/v projections via mma — fp32 inputs split in-kernel
    // (split_kernel eliminated)
    cudaFuncSetAttribute(qkvmma_kernel, cudaFuncAttributeMaxDynamicSharedMemorySize,
                         Q_SMEM);
    dim3 gq(NN / 128, 2, 3);
    qkvmma_kernel<<<gq, 256, Q_SMEM>>>(x, Wq, Wk, Wv, bq, bk, bv);

    // s partials: raw fp32 adj via cp.async + in-pipeline fp16 convert
    cudaFuncSetAttribute(smma_kernel, cudaFuncAttributeMaxDynamicSharedMemorySize,
                         S_SMEM);
    dim3 gs(NN / 128, 2, 2);
    smma_kernel<<<gs, 256, S_SMEM>>>(adj);

    // softmax (exp + 1/sum only; normalization fused into out_kernel)
    softmax_kernel<<<1, 1024>>>();

    // out = alpha[:,None] * v  (+ normalized alpha tail)
    int write_tail = (out_size >= NN * DD + NN) ? 1 : 0;
    int total = NN * DD / 4 + NN / 4;
    out_kernel<<<(total + 255) / 256, 256>>>(out, write_tail);
}